// round 5
// baseline (speedup 1.0000x reference)
#include <cuda_runtime.h>
#include <math.h>
#include <stdint.h>

// ---------------- static config ----------------
#define B_     8
#define C_     192
#define H_     128
#define W_     128
#define WS_    8
#define SHIFT_ 4
#define HEADS_ 4
#define HD_    48
#define L_     64
#define NW_    256                 // windows per image (16x16)
#define T_     (B_*NW_*L_)         // 131072 tokens
#define HID_   768

// ---------------- scratch (static device globals; no runtime allocation) ----
__device__ float g_xw [(size_t)T_ * C_];    // windowed shifted input (shortcut)
__device__ float g_xn [(size_t)T_ * C_];    // ln1 out -> attn out -> x2
__device__ float g_x1 [(size_t)T_ * C_];    // residual-1 output
__device__ float g_big[(size_t)T_ * HID_];  // qkv (576 cols) then mlp hidden (768)

enum Buf { BUF_XW = 0, BUF_XN = 1, BUF_X1 = 2, BUF_BIG = 3 };

__device__ __forceinline__ float* buf_ptr(int sel) {
    switch (sel) {
        case BUF_XW:  return g_xw;
        case BUF_XN:  return g_xn;
        case BUF_X1:  return g_x1;
        default:      return g_big;
    }
}

__device__ __forceinline__ uint32_t to_tf32(float f) {
    uint32_t r;
    asm("cvt.rna.tf32.f32 %0, %1;" : "=r"(r) : "f"(f));
    return r;
}

__device__ __forceinline__ void mma_tf32(float c[4],
                                         const uint32_t a[4], const uint32_t b[2]) {
    asm volatile(
        "mma.sync.aligned.m16n8k8.row.col.f32.tf32.tf32.f32 "
        "{%0,%1,%2,%3}, {%4,%5,%6,%7}, {%8,%9}, {%0,%1,%2,%3};"
        : "+f"(c[0]), "+f"(c[1]), "+f"(c[2]), "+f"(c[3])
        : "r"(a[0]), "r"(a[1]), "r"(a[2]), "r"(a[3]), "r"(b[0]), "r"(b[1]));
}

// ---------------- gather: x(B,C,H,W) --roll(-4,-4)+window--> g_xw[T][C] -----
__global__ __launch_bounds__(256) void gather_kernel(const float* __restrict__ x) {
    __shared__ float s[48 * 65];
    int blk = blockIdx.x;            // b*NW + n
    int b = blk / NW_;
    int n = blk % NW_;
    int wh = n >> 4, ww = n & 15;
    long tokbase = (long)blk * L_;
    int tid = threadIdx.x;
    for (int ci = 0; ci < 4; ci++) {          // 4 chunks of 48 channels
        #pragma unroll
        for (int t = 0; t < 12; t++) {
            int idx = tid + t * 256;          // 0..3071
            int c = idx >> 6, l = idx & 63;
            int hr = (wh * 8 + (l >> 3) + SHIFT_) & 127;
            int wc = (ww * 8 + (l & 7) + SHIFT_) & 127;
            s[c * 65 + l] = x[(((b * C_ + ci * 48 + c) * H_ + hr) << 7) + wc];
        }
        __syncthreads();
        #pragma unroll
        for (int t = 0; t < 12; t++) {
            int idx = tid + t * 256;
            int l = idx / 48, c = idx % 48;
            g_xw[(tokbase + l) * C_ + ci * 48 + c] = s[c * 65 + l];
        }
        __syncthreads();
    }
}

// ---------------- scatter: g_xn[T][C] --reverse window + roll(+4,+4)--> out -
__global__ __launch_bounds__(256) void scatter_kernel(float* __restrict__ out) {
    __shared__ float s[48 * 65];
    int blk = blockIdx.x;
    int b = blk / NW_;
    int n = blk % NW_;
    int wh = n >> 4, ww = n & 15;
    long tokbase = (long)blk * L_;
    int tid = threadIdx.x;
    for (int ci = 0; ci < 4; ci++) {
        #pragma unroll
        for (int t = 0; t < 12; t++) {
            int idx = tid + t * 256;
            int l = idx / 48, c = idx % 48;
            s[c * 65 + l] = g_xn[(tokbase + l) * C_ + ci * 48 + c];
        }
        __syncthreads();
        #pragma unroll
        for (int t = 0; t < 12; t++) {
            int idx = tid + t * 256;
            int c = idx >> 6, l = idx & 63;
            int hr = (wh * 8 + (l >> 3) + SHIFT_) & 127;
            int wc = (ww * 8 + (l & 7) + SHIFT_) & 127;
            out[(((b * C_ + ci * 48 + c) * H_ + hr) << 7) + wc] = s[c * 65 + l];
        }
        __syncthreads();
    }
}

// ---------------- layernorm: warp per token over C=192 ----------------------
__global__ __launch_bounds__(256) void ln_sym(int selI, int selO,
                                              const float* __restrict__ gam,
                                              const float* __restrict__ bet) {
    const float* in = buf_ptr(selI);
    float* out = buf_ptr(selO);
    int warp = threadIdx.x >> 5;
    int lane = threadIdx.x & 31;
    long tok = (long)blockIdx.x * 8 + warp;
    const float* row = in + tok * C_;
    float v[6];
    float sum = 0.f;
    #pragma unroll
    for (int u = 0; u < 6; u++) { v[u] = row[lane + 32 * u]; sum += v[u]; }
    #pragma unroll
    for (int o = 16; o; o >>= 1) sum += __shfl_xor_sync(0xffffffffu, sum, o);
    float mu = sum * (1.0f / 192.0f);
    float sq = 0.f;
    #pragma unroll
    for (int u = 0; u < 6; u++) { float d = v[u] - mu; sq += d * d; }
    #pragma unroll
    for (int o = 16; o; o >>= 1) sq += __shfl_xor_sync(0xffffffffu, sq, o);
    float rstd = rsqrtf(sq * (1.0f / 192.0f) + 1e-5f);
    float* orow = out + tok * C_;
    #pragma unroll
    for (int u = 0; u < 6; u++) {
        int c = lane + 32 * u;
        orow[c] = (v[u] - mu) * rstd * gam[c] + bet[c];
    }
}

// ---------------- TF32 tensor-core GEMM, K-chunk 32, reg-staged pipeline ----
enum { OP_BIAS = 0, OP_BIAS_RES = 1, OP_BIAS_GELU = 2 };

template<int OP>
__global__ __launch_bounds__(256) void tgemm_sym(int selA, int selR, int selO,
                                                 const float* __restrict__ Wm,
                                                 const float* __restrict__ bias,
                                                 int M, int N, int K) {
    const float* A = buf_ptr(selA);
    const float* R = buf_ptr(selR);
    float* O = buf_ptr(selO);

    __shared__ uint32_t As[32][136];   // [k][m], stride 136 ≡ 8 mod 32 (conflict-free)
    __shared__ uint32_t Bs[32][72];    // [k][n], stride 72  ≡ 8 mod 32

    int tid = threadIdx.x;
    int warp = tid >> 5;
    int lane = tid & 31;
    int gid = lane >> 2;               // 0..7
    int tig = lane & 3;                // 0..3
    int wm = (warp >> 1) * 32;         // 0,32,64,96
    int wn = (warp & 1) * 32;          // 0,32
    int m0 = blockIdx.y * 128;
    int n0 = blockIdx.x * 64;

    // per-thread load coordinates (fixed across iterations)
    int arow[4], akq[4];
    #pragma unroll
    for (int i = 0; i < 4; i++) {
        int idx = tid + i * 256;       // 0..1023 float4s (128 rows x 8)
        arow[i] = idx >> 3;
        akq[i] = idx & 7;
    }
    int brow[2], bcq[2];
    #pragma unroll
    for (int i = 0; i < 2; i++) {
        int idx = tid + i * 256;       // 0..511 float4s (32 rows x 16)
        brow[i] = idx >> 4;
        bcq[i] = idx & 15;
    }

    float acc[2][4][4];
    #pragma unroll
    for (int i = 0; i < 2; i++)
        #pragma unroll
        for (int j = 0; j < 4; j++)
            #pragma unroll
            for (int c = 0; c < 4; c++) acc[i][j][c] = 0.f;

    float4 ra[4], rb[2];
    // prefetch k0 = 0
    #pragma unroll
    for (int i = 0; i < 4; i++)
        ra[i] = *(const float4*)(A + (long)(m0 + arow[i]) * K + akq[i] * 4);
    #pragma unroll
    for (int i = 0; i < 2; i++)
        rb[i] = *(const float4*)(Wm + (long)brow[i] * N + n0 + bcq[i] * 4);

    for (int k0 = 0; k0 < K; k0 += 32) {
        // store staged registers into smem (tf32 convert)
        #pragma unroll
        for (int i = 0; i < 4; i++) {
            int kk = akq[i] * 4, row = arow[i];
            As[kk + 0][row] = to_tf32(ra[i].x);
            As[kk + 1][row] = to_tf32(ra[i].y);
            As[kk + 2][row] = to_tf32(ra[i].z);
            As[kk + 3][row] = to_tf32(ra[i].w);
        }
        #pragma unroll
        for (int i = 0; i < 2; i++) {
            int cc = bcq[i] * 4, row = brow[i];
            Bs[row][cc + 0] = to_tf32(rb[i].x);
            Bs[row][cc + 1] = to_tf32(rb[i].y);
            Bs[row][cc + 2] = to_tf32(rb[i].z);
            Bs[row][cc + 3] = to_tf32(rb[i].w);
        }
        __syncthreads();

        // prefetch next chunk while computing this one
        int kn = k0 + 32;
        if (kn < K) {
            #pragma unroll
            for (int i = 0; i < 4; i++)
                ra[i] = *(const float4*)(A + (long)(m0 + arow[i]) * K + kn + akq[i] * 4);
            #pragma unroll
            for (int i = 0; i < 2; i++)
                rb[i] = *(const float4*)(Wm + (long)(kn + brow[i]) * N + n0 + bcq[i] * 4);
        }

        #pragma unroll
        for (int ks = 0; ks < 4; ks++) {
            int kb = ks * 8;
            uint32_t a[2][4], b[4][2];
            #pragma unroll
            for (int mi = 0; mi < 2; mi++) {
                int mrow = wm + mi * 16 + gid;
                a[mi][0] = As[kb + tig][mrow];
                a[mi][1] = As[kb + tig][mrow + 8];
                a[mi][2] = As[kb + tig + 4][mrow];
                a[mi][3] = As[kb + tig + 4][mrow + 8];
            }
            #pragma unroll
            for (int ni = 0; ni < 4; ni++) {
                int ncol = wn + ni * 8 + gid;
                b[ni][0] = Bs[kb + tig][ncol];
                b[ni][1] = Bs[kb + tig + 4][ncol];
            }
            #pragma unroll
            for (int mi = 0; mi < 2; mi++)
                #pragma unroll
                for (int ni = 0; ni < 4; ni++)
                    mma_tf32(acc[mi][ni], a[mi], b[ni]);
        }
        __syncthreads();
    }

    #pragma unroll
    for (int mi = 0; mi < 2; mi++) {
        #pragma unroll
        for (int ni = 0; ni < 4; ni++) {
            int col = n0 + wn + ni * 8 + tig * 2;
            float bv0 = bias[col], bv1 = bias[col + 1];
            #pragma unroll
            for (int h = 0; h < 2; h++) {
                long row = m0 + wm + mi * 16 + gid + h * 8;
                float v0 = acc[mi][ni][h * 2 + 0] + bv0;
                float v1 = acc[mi][ni][h * 2 + 1] + bv1;
                if (OP == OP_BIAS_GELU) {
                    v0 = 0.5f * v0 * (1.0f + erff(v0 * 0.70710678118654752f));
                    v1 = 0.5f * v1 * (1.0f + erff(v1 * 0.70710678118654752f));
                }
                if (OP == OP_BIAS_RES) {
                    v0 += R[row * N + col];
                    v1 += R[row * N + col + 1];
                }
                float2 o = make_float2(v0, v1);
                *(float2*)(O + row * N + col) = o;
            }
        }
    }
}

// ---------------- tensor-core windowed attention ----------------------------
// one 128-thread block per (b, window, head); 4 warps, 16 rows each
#define QK_STR 72   // ≡ 8 mod 32 -> conflict-free B/A fragment loads
#define V_STR  56   // ≡ 24 mod 32 -> conflict-free
#define P_STR  68   // ≡ 4 mod 32 -> conflict-free A fragment loads

__global__ __launch_bounds__(128) void attn_mma_kernel(const float* __restrict__ bias_table) {
    __shared__ uint32_t sQK[2 * 48 * QK_STR];   // Q at 0, K at 3456; reused as P
    __shared__ uint32_t sV[64 * V_STR];
    __shared__ float bb[225];

    uint32_t* sQ = sQK;
    uint32_t* sK = sQK + 48 * QK_STR;
    uint32_t* sP = sQK;

    int blk = blockIdx.x;            // (b*NW + n)*HEADS + head
    int head = blk & 3;
    int bn = blk >> 2;
    int n = bn % NW_;
    int wh = n >> 4, ww = n & 15;
    long tokbase = (long)bn * 64;
    int tid = threadIdx.x;
    int warp = tid >> 5;
    int lane = tid & 31;
    int gid = lane >> 2;             // 0..7
    int tig = lane & 3;              // 0..3

    for (int t = tid; t < 225; t += 128) bb[t] = bias_table[head * 225 + t];

    const float scale = 0.14433756729740643f;   // 1/sqrt(48)
    for (int t = tid; t < 768; t += 128) {       // 64 rows x 12 float4
        int l = t / 12, q4 = t % 12, d = q4 * 4;
        const float* base = g_big + (tokbase + l) * 576 + head * 48 + d;
        float4 q = *(const float4*)(base);
        float4 k = *(const float4*)(base + 192);
        float4 v = *(const float4*)(base + 384);
        sQ[(d + 0) * QK_STR + l] = to_tf32(q.x * scale);
        sQ[(d + 1) * QK_STR + l] = to_tf32(q.y * scale);
        sQ[(d + 2) * QK_STR + l] = to_tf32(q.z * scale);
        sQ[(d + 3) * QK_STR + l] = to_tf32(q.w * scale);
        sK[(d + 0) * QK_STR + l] = to_tf32(k.x);
        sK[(d + 1) * QK_STR + l] = to_tf32(k.y);
        sK[(d + 2) * QK_STR + l] = to_tf32(k.z);
        sK[(d + 3) * QK_STR + l] = to_tf32(k.w);
        uint4 vv = make_uint4(to_tf32(v.x), to_tf32(v.y), to_tf32(v.z), to_tf32(v.w));
        *(uint4*)&sV[l * V_STR + d] = vv;
    }
    __syncthreads();

    int r0 = warp * 16 + gid;
    float acc[8][4];
    #pragma unroll
    for (int ni = 0; ni < 8; ni++)
        #pragma unroll
        for (int c = 0; c < 4; c++) acc[ni][c] = 0.f;

    #pragma unroll
    for (int kb = 0; kb < 6; kb++) {
        int k = kb * 8;
        uint32_t a[4];
        a[0] = sQ[(k + tig) * QK_STR + r0];
        a[1] = sQ[(k + tig) * QK_STR + r0 + 8];
        a[2] = sQ[(k + tig + 4) * QK_STR + r0];
        a[3] = sQ[(k + tig + 4) * QK_STR + r0 + 8];
        #pragma unroll
        for (int ni = 0; ni < 8; ni++) {
            uint32_t b[2];
            b[0] = sK[(k + tig) * QK_STR + ni * 8 + gid];
            b[1] = sK[(k + tig + 4) * QK_STR + ni * 8 + gid];
            mma_tf32(acc[ni], a, b);
        }
    }

    int ih0 = r0 >> 3, iw0 = r0 & 7;
    int r1 = r0 + 8;
    int ih1 = r1 >> 3, iw1 = r1 & 7;
    int reg_i0 = ((wh == 15) ? (ih0 < 4 ? 3 : 6) : 0) + ((ww == 15) ? (iw0 < 4 ? 1 : 2) : 0);
    int reg_i1 = ((wh == 15) ? (ih1 < 4 ? 3 : 6) : 0) + ((ww == 15) ? (iw1 < 4 ? 1 : 2) : 0);

    float mx0 = -1e30f, mx1 = -1e30f;
    #pragma unroll
    for (int ni = 0; ni < 8; ni++) {
        #pragma unroll
        for (int hh = 0; hh < 2; hh++) {
            int j = ni * 8 + tig * 2 + hh;
            int jh = j >> 3, jw = j & 7;
            int reg_j = ((wh == 15) ? (jh < 4 ? 3 : 6) : 0) + ((ww == 15) ? (jw < 4 ? 1 : 2) : 0);
            float bt0 = (reg_i0 != reg_j) ? -100.0f : bb[(ih0 - jh + 7) * 15 + (iw0 - jw + 7)];
            float bt1 = (reg_i1 != reg_j) ? -100.0f : bb[(ih1 - jh + 7) * 15 + (iw1 - jw + 7)];
            acc[ni][hh]     += bt0;
            acc[ni][2 + hh] += bt1;
            mx0 = fmaxf(mx0, acc[ni][hh]);
            mx1 = fmaxf(mx1, acc[ni][2 + hh]);
        }
    }
    mx0 = fmaxf(mx0, __shfl_xor_sync(0xffffffffu, mx0, 1));
    mx0 = fmaxf(mx0, __shfl_xor_sync(0xffffffffu, mx0, 2));
    mx1 = fmaxf(mx1, __shfl_xor_sync(0xffffffffu, mx1, 1));
    mx1 = fmaxf(mx1, __shfl_xor_sync(0xffffffffu, mx1, 2));
    float s0 = 0.f, s1 = 0.f;
    #pragma unroll
    for (int ni = 0; ni < 8; ni++) {
        #pragma unroll
        for (int hh = 0; hh < 2; hh++) {
            acc[ni][hh]     = __expf(acc[ni][hh] - mx0);     s0 += acc[ni][hh];
            acc[ni][2 + hh] = __expf(acc[ni][2 + hh] - mx1); s1 += acc[ni][2 + hh];
        }
    }
    s0 += __shfl_xor_sync(0xffffffffu, s0, 1);
    s0 += __shfl_xor_sync(0xffffffffu, s0, 2);
    s1 += __shfl_xor_sync(0xffffffffu, s1, 1);
    s1 += __shfl_xor_sync(0xffffffffu, s1, 2);
    float inv0 = 1.0f / s0, inv1 = 1.0f / s1;

    __syncthreads();

    #pragma unroll
    for (int ni = 0; ni < 8; ni++) {
        int j = ni * 8 + tig * 2;
        sP[r0 * P_STR + j]     = to_tf32(acc[ni][0] * inv0);
        sP[r0 * P_STR + j + 1] = to_tf32(acc[ni][1] * inv0);
        sP[r1 * P_STR + j]     = to_tf32(acc[ni][2] * inv1);
        sP[r1 * P_STR + j + 1] = to_tf32(acc[ni][3] * inv1);
    }
    __syncthreads();

    float oacc[6][4];
    #pragma unroll
    for (int ni = 0; ni < 6; ni++)
        #pragma unroll
        for (int c = 0; c < 4; c++) oacc[ni][c] = 0.f;

    #pragma unroll
    for (int kt = 0; kt < 8; kt++) {
        int k = kt * 8;
        uint32_t a[4];
        a[0] = sP[r0 * P_STR + k + tig];
        a[1] = sP[r1 * P_STR + k + tig];
        a[2] = sP[r0 * P_STR + k + tig + 4];
        a[3] = sP[r1 * P_STR + k + tig + 4];
        #pragma unroll
        for (int ni = 0; ni < 6; ni++) {
            uint32_t b[2];
            b[0] = sV[(k + tig) * V_STR + ni * 8 + gid];
            b[1] = sV[(k + tig + 4) * V_STR + ni * 8 + gid];
            mma_tf32(oacc[ni], a, b);
        }
    }

    #pragma unroll
    for (int ni = 0; ni < 6; ni++) {
        int col = ni * 8 + tig * 2;
        float* p0 = g_xn + (tokbase + r0) * C_ + head * 48 + col;
        float* p1 = g_xn + (tokbase + r1) * C_ + head * 48 + col;
        *(float2*)p0 = make_float2(oacc[ni][0], oacc[ni][1]);
        *(float2*)p1 = make_float2(oacc[ni][2], oacc[ni][3]);
    }
}

// ---------------- launcher ---------------------------------------------------
extern "C" void kernel_launch(void* const* d_in, const int* in_sizes, int n_in,
                              void* d_out, int out_size) {
    const float* x   = (const float*)d_in[0];
    const float* bt  = (const float*)d_in[1];
    const float* qw  = (const float*)d_in[2];
    const float* qb  = (const float*)d_in[3];
    const float* pw  = (const float*)d_in[4];
    const float* pb  = (const float*)d_in[5];
    const float* g1  = (const float*)d_in[6];
    const float* b1  = (const float*)d_in[7];
    const float* g2  = (const float*)d_in[8];
    const float* b2  = (const float*)d_in[9];
    const float* w1  = (const float*)d_in[10];
    const float* bb1 = (const float*)d_in[11];
    const float* w2  = (const float*)d_in[12];
    const float* bb2 = (const float*)d_in[13];
    float* out = (float*)d_out;

    // 1. shifted window partition  (x -> g_xw)
    gather_kernel<<<B_ * NW_, 256>>>(x);
    // 2. LN1 (g_xw -> g_xn)
    ln_sym<<<T_ / 8, 256>>>(BUF_XW, BUF_XN, g1, b1);
    // 3. QKV GEMM: [T,192] @ [192,576]  (g_xn -> g_big)
    tgemm_sym<OP_BIAS><<<dim3(576 / 64, T_ / 128), 256>>>(BUF_XN, BUF_XN, BUF_BIG, qw, qb, T_, 576, 192);
    // 4. tensor-core windowed attention (g_big -> g_xn, head-major C)
    attn_mma_kernel<<<B_ * NW_ * HEADS_, 128>>>(bt);
    // 5. proj GEMM + residual (g_xn @ pw + g_xw -> g_x1)
    tgemm_sym<OP_BIAS_RES><<<dim3(192 / 64, T_ / 128), 256>>>(BUF_XN, BUF_XW, BUF_X1, pw, pb, T_, 192, 192);
    // 6. LN2 (g_x1 -> g_xw)
    ln_sym<<<T_ / 8, 256>>>(BUF_X1, BUF_XW, g2, b2);
    // 7. MLP1 + exact GELU: [T,192] @ [192,768]  (g_xw -> g_big)
    tgemm_sym<OP_BIAS_GELU><<<dim3(768 / 64, T_ / 128), 256>>>(BUF_XW, BUF_XW, BUF_BIG, w1, bb1, T_, 768, 192);
    // 8. MLP2 + residual: [T,768] @ [768,192] + g_x1 -> g_xn
    tgemm_sym<OP_BIAS_RES><<<dim3(192 / 64, T_ / 128), 256>>>(BUF_BIG, BUF_X1, BUF_XN, w2, bb2, T_, 192, 768);
    // 9. window reverse + roll(+4,+4)  (g_xn -> out)
    scatter_kernel<<<B_ * NW_, 256>>>(out);
}

// round 6
// speedup vs baseline: 1.4386x; 1.4386x over previous
#include <cuda_runtime.h>
#include <math.h>
#include <stdint.h>

// ---------------- static config ----------------
#define B_     8
#define C_     192
#define H_     128
#define W_     128
#define WS_    8
#define SHIFT_ 4
#define HEADS_ 4
#define HD_    48
#define L_     64
#define NW_    256                 // windows per image (16x16)
#define T_     (B_*NW_*L_)         // 131072 tokens
#define HID_   768

// ---------------- scratch (static device globals; no runtime allocation) ----
__device__ float g_xw [(size_t)T_ * C_];    // windowed shifted input (shortcut)
__device__ float g_xn [(size_t)T_ * C_];    // ln1 out -> attn out -> x2
__device__ float g_x1 [(size_t)T_ * C_];    // residual-1 output
__device__ float g_big[(size_t)T_ * HID_];  // qkv (576 cols) then mlp hidden (768)

enum Buf { BUF_XW = 0, BUF_XN = 1, BUF_X1 = 2, BUF_BIG = 3 };

__device__ __forceinline__ float* buf_ptr(int sel) {
    switch (sel) {
        case BUF_XW:  return g_xw;
        case BUF_XN:  return g_xn;
        case BUF_X1:  return g_x1;
        default:      return g_big;
    }
}

__device__ __forceinline__ uint32_t to_tf32(float f) {
    uint32_t r;
    asm("cvt.rna.tf32.f32 %0, %1;" : "=r"(r) : "f"(f));
    return r;
}

__device__ __forceinline__ void mma_tf32(float c[4],
                                         const uint32_t a[4], const uint32_t b[2]) {
    asm volatile(
        "mma.sync.aligned.m16n8k8.row.col.f32.tf32.tf32.f32 "
        "{%0,%1,%2,%3}, {%4,%5,%6,%7}, {%8,%9}, {%0,%1,%2,%3};"
        : "+f"(c[0]), "+f"(c[1]), "+f"(c[2]), "+f"(c[3])
        : "r"(a[0]), "r"(a[1]), "r"(a[2]), "r"(a[3]), "r"(b[0]), "r"(b[1]));
}

__device__ __forceinline__ void cp_async16(void* smem, const void* gmem) {
    uint32_t s = (uint32_t)__cvta_generic_to_shared(smem);
    asm volatile("cp.async.ca.shared.global [%0], [%1], 16;" :: "r"(s), "l"(gmem));
}

// ---------------- gather: x(B,C,H,W) --roll(-4,-4)+window--> g_xw[T][C] -----
__global__ __launch_bounds__(256) void gather_kernel(const float* __restrict__ x) {
    __shared__ float s[48 * 65];
    int blk = blockIdx.x;            // b*NW + n
    int b = blk / NW_;
    int n = blk % NW_;
    int wh = n >> 4, ww = n & 15;
    long tokbase = (long)blk * L_;
    int tid = threadIdx.x;
    for (int ci = 0; ci < 4; ci++) {          // 4 chunks of 48 channels
        #pragma unroll
        for (int t = 0; t < 12; t++) {
            int idx = tid + t * 256;          // 0..3071
            int c = idx >> 6, l = idx & 63;
            int hr = (wh * 8 + (l >> 3) + SHIFT_) & 127;
            int wc = (ww * 8 + (l & 7) + SHIFT_) & 127;
            s[c * 65 + l] = x[(((b * C_ + ci * 48 + c) * H_ + hr) << 7) + wc];
        }
        __syncthreads();
        #pragma unroll
        for (int t = 0; t < 12; t++) {
            int idx = tid + t * 256;
            int l = idx / 48, c = idx % 48;
            g_xw[(tokbase + l) * C_ + ci * 48 + c] = s[c * 65 + l];
        }
        __syncthreads();
    }
}

// ---------------- scatter: g_xn[T][C] --reverse window + roll(+4,+4)--> out -
__global__ __launch_bounds__(256) void scatter_kernel(float* __restrict__ out) {
    __shared__ float s[48 * 65];
    int blk = blockIdx.x;
    int b = blk / NW_;
    int n = blk % NW_;
    int wh = n >> 4, ww = n & 15;
    long tokbase = (long)blk * L_;
    int tid = threadIdx.x;
    for (int ci = 0; ci < 4; ci++) {
        #pragma unroll
        for (int t = 0; t < 12; t++) {
            int idx = tid + t * 256;
            int l = idx / 48, c = idx % 48;
            s[c * 65 + l] = g_xn[(tokbase + l) * C_ + ci * 48 + c];
        }
        __syncthreads();
        #pragma unroll
        for (int t = 0; t < 12; t++) {
            int idx = tid + t * 256;
            int c = idx >> 6, l = idx & 63;
            int hr = (wh * 8 + (l >> 3) + SHIFT_) & 127;
            int wc = (ww * 8 + (l & 7) + SHIFT_) & 127;
            out[(((b * C_ + ci * 48 + c) * H_ + hr) << 7) + wc] = s[c * 65 + l];
        }
        __syncthreads();
    }
}

// ---------------- layernorm: warp per token over C=192 ----------------------
__global__ __launch_bounds__(256) void ln_sym(int selI, int selO,
                                              const float* __restrict__ gam,
                                              const float* __restrict__ bet) {
    const float* in = buf_ptr(selI);
    float* out = buf_ptr(selO);
    int warp = threadIdx.x >> 5;
    int lane = threadIdx.x & 31;
    long tok = (long)blockIdx.x * 8 + warp;
    const float* row = in + tok * C_;
    float v[6];
    float sum = 0.f;
    #pragma unroll
    for (int u = 0; u < 6; u++) { v[u] = row[lane + 32 * u]; sum += v[u]; }
    #pragma unroll
    for (int o = 16; o; o >>= 1) sum += __shfl_xor_sync(0xffffffffu, sum, o);
    float mu = sum * (1.0f / 192.0f);
    float sq = 0.f;
    #pragma unroll
    for (int u = 0; u < 6; u++) { float d = v[u] - mu; sq += d * d; }
    #pragma unroll
    for (int o = 16; o; o >>= 1) sq += __shfl_xor_sync(0xffffffffu, sq, o);
    float rstd = rsqrtf(sq * (1.0f / 192.0f) + 1e-5f);
    float* orow = out + tok * C_;
    #pragma unroll
    for (int u = 0; u < 6; u++) {
        int c = lane + 32 * u;
        orow[c] = (v[u] - mu) * rstd * gam[c] + bet[c];
    }
}

// ---------------- TF32 tensor-core GEMM, cp.async double-buffered -----------
// K-chunk 16. A tile row-major [128][20] (stride 20: gid*20+tig mod 32 all
// distinct -> conflict-free fragment loads). B tile [16][72] as before.
// Smem holds raw fp32 bits; mma.tf32 truncates mantissa (no cvt in hot path).
enum { OP_BIAS = 0, OP_BIAS_RES = 1, OP_BIAS_GELU = 2 };

template<int OP>
__global__ __launch_bounds__(256) void tgemm_sym(int selA, int selR, int selO,
                                                 const float* __restrict__ Wm,
                                                 const float* __restrict__ bias,
                                                 int M, int N, int K) {
    const float* A = buf_ptr(selA);
    const float* R = buf_ptr(selR);
    float* O = buf_ptr(selO);

    __shared__ uint32_t As[2][128][20];
    __shared__ uint32_t Bs[2][16][72];

    int tid = threadIdx.x;
    int warp = tid >> 5;
    int lane = tid & 31;
    int gid = lane >> 2;               // 0..7
    int tig = lane & 3;                // 0..3
    int wm = (warp >> 1) * 32;         // 0,32,64,96
    int wn = (warp & 1) * 32;          // 0,32
    int m0 = blockIdx.y * 128;
    int n0 = blockIdx.x * 64;

    int a_row0 = tid >> 2, a_q = tid & 3;       // chunks 0..255
    int a_row1 = (tid + 256) >> 2;              // chunks 256..511 (same q)
    int b_row = tid >> 4, b_q = tid & 15;

    float acc[2][4][4];
    #pragma unroll
    for (int i = 0; i < 2; i++)
        #pragma unroll
        for (int j = 0; j < 4; j++)
            #pragma unroll
            for (int c = 0; c < 4; c++) acc[i][j][c] = 0.f;

    const int NKC = K >> 4;

    // prefetch chunk 0 into buffer 0
    cp_async16(&As[0][a_row0][a_q * 4], A + (long)(m0 + a_row0) * K + a_q * 4);
    cp_async16(&As[0][a_row1][a_q * 4], A + (long)(m0 + a_row1) * K + a_q * 4);
    cp_async16(&Bs[0][b_row][b_q * 4], Wm + (long)b_row * N + n0 + b_q * 4);
    asm volatile("cp.async.commit_group;");

    int bf = 0;
    for (int it = 0; it < NKC; it++) {
        if (it + 1 < NKC) {
            int kk = (it + 1) << 4;
            int nb = bf ^ 1;
            cp_async16(&As[nb][a_row0][a_q * 4], A + (long)(m0 + a_row0) * K + kk + a_q * 4);
            cp_async16(&As[nb][a_row1][a_q * 4], A + (long)(m0 + a_row1) * K + kk + a_q * 4);
            cp_async16(&Bs[nb][b_row][b_q * 4], Wm + (long)(kk + b_row) * N + n0 + b_q * 4);
            asm volatile("cp.async.commit_group;");
            asm volatile("cp.async.wait_group 1;");
        } else {
            asm volatile("cp.async.wait_group 0;");
        }
        __syncthreads();

        #pragma unroll
        for (int ks = 0; ks < 2; ks++) {
            int kb = ks * 8;
            uint32_t a[2][4], b[4][2];
            #pragma unroll
            for (int mi = 0; mi < 2; mi++) {
                int mrow = wm + mi * 16 + gid;
                a[mi][0] = As[bf][mrow][kb + tig];
                a[mi][1] = As[bf][mrow + 8][kb + tig];
                a[mi][2] = As[bf][mrow][kb + tig + 4];
                a[mi][3] = As[bf][mrow + 8][kb + tig + 4];
            }
            #pragma unroll
            for (int ni = 0; ni < 4; ni++) {
                int ncol = wn + ni * 8 + gid;
                b[ni][0] = Bs[bf][kb + tig][ncol];
                b[ni][1] = Bs[bf][kb + tig + 4][ncol];
            }
            #pragma unroll
            for (int mi = 0; mi < 2; mi++)
                #pragma unroll
                for (int ni = 0; ni < 4; ni++)
                    mma_tf32(acc[mi][ni], a[mi], b[ni]);
        }
        bf ^= 1;
        __syncthreads();
    }

    #pragma unroll
    for (int mi = 0; mi < 2; mi++) {
        #pragma unroll
        for (int ni = 0; ni < 4; ni++) {
            int col = n0 + wn + ni * 8 + tig * 2;
            float bv0 = bias[col], bv1 = bias[col + 1];
            #pragma unroll
            for (int h = 0; h < 2; h++) {
                long row = m0 + wm + mi * 16 + gid + h * 8;
                float v0 = acc[mi][ni][h * 2 + 0] + bv0;
                float v1 = acc[mi][ni][h * 2 + 1] + bv1;
                if (OP == OP_BIAS_GELU) {
                    v0 = 0.5f * v0 * (1.0f + erff(v0 * 0.70710678118654752f));
                    v1 = 0.5f * v1 * (1.0f + erff(v1 * 0.70710678118654752f));
                }
                if (OP == OP_BIAS_RES) {
                    v0 += R[row * N + col];
                    v1 += R[row * N + col + 1];
                }
                float2 o = make_float2(v0, v1);
                *(float2*)(O + row * N + col) = o;
            }
        }
    }
}

// ---------------- tensor-core windowed attention ----------------------------
// one 128-thread block per (b, window, head); 4 warps, 16 rows each
#define QK_STR 72   // ≡ 8 mod 32 -> conflict-free B/A fragment loads
#define V_STR  56   // ≡ 24 mod 32 -> conflict-free
#define P_STR  68   // ≡ 4 mod 32 -> conflict-free A fragment loads

__global__ __launch_bounds__(128) void attn_mma_kernel(const float* __restrict__ bias_table) {
    __shared__ uint32_t sQK[2 * 48 * QK_STR];   // Q at 0, K at 3456; reused as P
    __shared__ uint32_t sV[64 * V_STR];
    __shared__ float bb[225];

    uint32_t* sQ = sQK;
    uint32_t* sK = sQK + 48 * QK_STR;
    uint32_t* sP = sQK;

    int blk = blockIdx.x;            // (b*NW + n)*HEADS + head
    int head = blk & 3;
    int bn = blk >> 2;
    int n = bn % NW_;
    int wh = n >> 4, ww = n & 15;
    long tokbase = (long)bn * 64;
    int tid = threadIdx.x;
    int warp = tid >> 5;
    int lane = tid & 31;
    int gid = lane >> 2;             // 0..7
    int tig = lane & 3;              // 0..3

    for (int t = tid; t < 225; t += 128) bb[t] = bias_table[head * 225 + t];

    const float scale = 0.14433756729740643f;   // 1/sqrt(48)
    for (int t = tid; t < 768; t += 128) {       // 64 rows x 12 float4
        int l = t / 12, q4 = t % 12, d = q4 * 4;
        const float* base = g_big + (tokbase + l) * 576 + head * 48 + d;
        float4 q = *(const float4*)(base);
        float4 k = *(const float4*)(base + 192);
        float4 v = *(const float4*)(base + 384);
        sQ[(d + 0) * QK_STR + l] = to_tf32(q.x * scale);
        sQ[(d + 1) * QK_STR + l] = to_tf32(q.y * scale);
        sQ[(d + 2) * QK_STR + l] = to_tf32(q.z * scale);
        sQ[(d + 3) * QK_STR + l] = to_tf32(q.w * scale);
        sK[(d + 0) * QK_STR + l] = to_tf32(k.x);
        sK[(d + 1) * QK_STR + l] = to_tf32(k.y);
        sK[(d + 2) * QK_STR + l] = to_tf32(k.z);
        sK[(d + 3) * QK_STR + l] = to_tf32(k.w);
        uint4 vv = make_uint4(to_tf32(v.x), to_tf32(v.y), to_tf32(v.z), to_tf32(v.w));
        *(uint4*)&sV[l * V_STR + d] = vv;
    }
    __syncthreads();

    int r0 = warp * 16 + gid;
    float acc[8][4];
    #pragma unroll
    for (int ni = 0; ni < 8; ni++)
        #pragma unroll
        for (int c = 0; c < 4; c++) acc[ni][c] = 0.f;

    #pragma unroll
    for (int kb = 0; kb < 6; kb++) {
        int k = kb * 8;
        uint32_t a[4];
        a[0] = sQ[(k + tig) * QK_STR + r0];
        a[1] = sQ[(k + tig) * QK_STR + r0 + 8];
        a[2] = sQ[(k + tig + 4) * QK_STR + r0];
        a[3] = sQ[(k + tig + 4) * QK_STR + r0 + 8];
        #pragma unroll
        for (int ni = 0; ni < 8; ni++) {
            uint32_t b[2];
            b[0] = sK[(k + tig) * QK_STR + ni * 8 + gid];
            b[1] = sK[(k + tig + 4) * QK_STR + ni * 8 + gid];
            mma_tf32(acc[ni], a, b);
        }
    }

    int ih0 = r0 >> 3, iw0 = r0 & 7;
    int r1 = r0 + 8;
    int ih1 = r1 >> 3, iw1 = r1 & 7;
    int reg_i0 = ((wh == 15) ? (ih0 < 4 ? 3 : 6) : 0) + ((ww == 15) ? (iw0 < 4 ? 1 : 2) : 0);
    int reg_i1 = ((wh == 15) ? (ih1 < 4 ? 3 : 6) : 0) + ((ww == 15) ? (iw1 < 4 ? 1 : 2) : 0);

    float mx0 = -1e30f, mx1 = -1e30f;
    #pragma unroll
    for (int ni = 0; ni < 8; ni++) {
        #pragma unroll
        for (int hh = 0; hh < 2; hh++) {
            int j = ni * 8 + tig * 2 + hh;
            int jh = j >> 3, jw = j & 7;
            int reg_j = ((wh == 15) ? (jh < 4 ? 3 : 6) : 0) + ((ww == 15) ? (jw < 4 ? 1 : 2) : 0);
            float bt0 = (reg_i0 != reg_j) ? -100.0f : bb[(ih0 - jh + 7) * 15 + (iw0 - jw + 7)];
            float bt1 = (reg_i1 != reg_j) ? -100.0f : bb[(ih1 - jh + 7) * 15 + (iw1 - jw + 7)];
            acc[ni][hh]     += bt0;
            acc[ni][2 + hh] += bt1;
            mx0 = fmaxf(mx0, acc[ni][hh]);
            mx1 = fmaxf(mx1, acc[ni][2 + hh]);
        }
    }
    mx0 = fmaxf(mx0, __shfl_xor_sync(0xffffffffu, mx0, 1));
    mx0 = fmaxf(mx0, __shfl_xor_sync(0xffffffffu, mx0, 2));
    mx1 = fmaxf(mx1, __shfl_xor_sync(0xffffffffu, mx1, 1));
    mx1 = fmaxf(mx1, __shfl_xor_sync(0xffffffffu, mx1, 2));
    float s0 = 0.f, s1 = 0.f;
    #pragma unroll
    for (int ni = 0; ni < 8; ni++) {
        #pragma unroll
        for (int hh = 0; hh < 2; hh++) {
            acc[ni][hh]     = __expf(acc[ni][hh] - mx0);     s0 += acc[ni][hh];
            acc[ni][2 + hh] = __expf(acc[ni][2 + hh] - mx1); s1 += acc[ni][2 + hh];
        }
    }
    s0 += __shfl_xor_sync(0xffffffffu, s0, 1);
    s0 += __shfl_xor_sync(0xffffffffu, s0, 2);
    s1 += __shfl_xor_sync(0xffffffffu, s1, 1);
    s1 += __shfl_xor_sync(0xffffffffu, s1, 2);
    float inv0 = 1.0f / s0, inv1 = 1.0f / s1;

    __syncthreads();

    #pragma unroll
    for (int ni = 0; ni < 8; ni++) {
        int j = ni * 8 + tig * 2;
        sP[r0 * P_STR + j]     = to_tf32(acc[ni][0] * inv0);
        sP[r0 * P_STR + j + 1] = to_tf32(acc[ni][1] * inv0);
        sP[r1 * P_STR + j]     = to_tf32(acc[ni][2] * inv1);
        sP[r1 * P_STR + j + 1] = to_tf32(acc[ni][3] * inv1);
    }
    __syncthreads();

    float oacc[6][4];
    #pragma unroll
    for (int ni = 0; ni < 6; ni++)
        #pragma unroll
        for (int c = 0; c < 4; c++) oacc[ni][c] = 0.f;

    #pragma unroll
    for (int kt = 0; kt < 8; kt++) {
        int k = kt * 8;
        uint32_t a[4];
        a[0] = sP[r0 * P_STR + k + tig];
        a[1] = sP[r1 * P_STR + k + tig];
        a[2] = sP[r0 * P_STR + k + tig + 4];
        a[3] = sP[r1 * P_STR + k + tig + 4];
        #pragma unroll
        for (int ni = 0; ni < 6; ni++) {
            uint32_t b[2];
            b[0] = sV[(k + tig) * V_STR + ni * 8 + gid];
            b[1] = sV[(k + tig + 4) * V_STR + ni * 8 + gid];
            mma_tf32(oacc[ni], a, b);
        }
    }

    #pragma unroll
    for (int ni = 0; ni < 6; ni++) {
        int col = ni * 8 + tig * 2;
        float* p0 = g_xn + (tokbase + r0) * C_ + head * 48 + col;
        float* p1 = g_xn + (tokbase + r1) * C_ + head * 48 + col;
        *(float2*)p0 = make_float2(oacc[ni][0], oacc[ni][1]);
        *(float2*)p1 = make_float2(oacc[ni][2], oacc[ni][3]);
    }
}

// ---------------- launcher ---------------------------------------------------
extern "C" void kernel_launch(void* const* d_in, const int* in_sizes, int n_in,
                              void* d_out, int out_size) {
    const float* x   = (const float*)d_in[0];
    const float* bt  = (const float*)d_in[1];
    const float* qw  = (const float*)d_in[2];
    const float* qb  = (const float*)d_in[3];
    const float* pw  = (const float*)d_in[4];
    const float* pb  = (const float*)d_in[5];
    const float* g1  = (const float*)d_in[6];
    const float* b1  = (const float*)d_in[7];
    const float* g2  = (const float*)d_in[8];
    const float* b2  = (const float*)d_in[9];
    const float* w1  = (const float*)d_in[10];
    const float* bb1 = (const float*)d_in[11];
    const float* w2  = (const float*)d_in[12];
    const float* bb2 = (const float*)d_in[13];
    float* out = (float*)d_out;

    // 1. shifted window partition  (x -> g_xw)
    gather_kernel<<<B_ * NW_, 256>>>(x);
    // 2. LN1 (g_xw -> g_xn)
    ln_sym<<<T_ / 8, 256>>>(BUF_XW, BUF_XN, g1, b1);
    // 3. QKV GEMM: [T,192] @ [192,576]  (g_xn -> g_big)
    tgemm_sym<OP_BIAS><<<dim3(576 / 64, T_ / 128), 256>>>(BUF_XN, BUF_XN, BUF_BIG, qw, qb, T_, 576, 192);
    // 4. tensor-core windowed attention (g_big -> g_xn, head-major C)
    attn_mma_kernel<<<B_ * NW_ * HEADS_, 128>>>(bt);
    // 5. proj GEMM + residual (g_xn @ pw + g_xw -> g_x1)
    tgemm_sym<OP_BIAS_RES><<<dim3(192 / 64, T_ / 128), 256>>>(BUF_XN, BUF_XW, BUF_X1, pw, pb, T_, 192, 192);
    // 6. LN2 (g_x1 -> g_xw)
    ln_sym<<<T_ / 8, 256>>>(BUF_X1, BUF_XW, g2, b2);
    // 7. MLP1 + exact GELU: [T,192] @ [192,768]  (g_xw -> g_big)
    tgemm_sym<OP_BIAS_GELU><<<dim3(768 / 64, T_ / 128), 256>>>(BUF_XW, BUF_XW, BUF_BIG, w1, bb1, T_, 768, 192);
    // 8. MLP2 + residual: [T,768] @ [768,192] + g_x1 -> g_xn
    tgemm_sym<OP_BIAS_RES><<<dim3(192 / 64, T_ / 128), 256>>>(BUF_BIG, BUF_X1, BUF_XN, w2, bb2, T_, 192, 768);
    // 9. window reverse + roll(+4,+4)  (g_xn -> out)
    scatter_kernel<<<B_ * NW_, 256>>>(out);
}

// round 8
// speedup vs baseline: 1.4410x; 1.0016x over previous
#include <cuda_runtime.h>
#include <math.h>
#include <stdint.h>

// ---------------- static config ----------------
#define B_     8
#define C_     192
#define H_     128
#define W_     128
#define WS_    8
#define SHIFT_ 4
#define HEADS_ 4
#define HD_    48
#define L_     64
#define NW_    256                 // windows per image (16x16)
#define T_     (B_*NW_*L_)         // 131072 tokens
#define HID_   768

// ---------------- scratch (static device globals; no runtime allocation) ----
__device__ float g_xw [(size_t)T_ * C_];    // windowed shifted input (shortcut)
__device__ float g_xn [(size_t)T_ * C_];    // ln1 out -> attn out -> x2
__device__ float g_x1 [(size_t)T_ * C_];    // residual-1 output
__device__ float g_big[(size_t)T_ * HID_];  // qkv (576 cols) then mlp hidden (768)

enum Buf { BUF_XW = 0, BUF_XN = 1, BUF_X1 = 2, BUF_BIG = 3 };

__device__ __forceinline__ float* buf_ptr(int sel) {
    switch (sel) {
        case BUF_XW:  return g_xw;
        case BUF_XN:  return g_xn;
        case BUF_X1:  return g_x1;
        default:      return g_big;
    }
}

__device__ __forceinline__ uint32_t to_tf32(float f) {
    uint32_t r;
    asm("cvt.rna.tf32.f32 %0, %1;" : "=r"(r) : "f"(f));
    return r;
}

__device__ __forceinline__ void mma_tf32(float c[4],
                                         const uint32_t a[4], const uint32_t b[2]) {
    asm volatile(
        "mma.sync.aligned.m16n8k8.row.col.f32.tf32.tf32.f32 "
        "{%0,%1,%2,%3}, {%4,%5,%6,%7}, {%8,%9}, {%0,%1,%2,%3};"
        : "+f"(c[0]), "+f"(c[1]), "+f"(c[2]), "+f"(c[3])
        : "r"(a[0]), "r"(a[1]), "r"(a[2]), "r"(a[3]), "r"(b[0]), "r"(b[1]));
}

__device__ __forceinline__ void cp_async16(void* smem, const void* gmem) {
    uint32_t s = (uint32_t)__cvta_generic_to_shared(smem);
    asm volatile("cp.async.ca.shared.global [%0], [%1], 16;" :: "r"(s), "l"(gmem));
}

// ---------------- fused gather + LN1 ----------------------------------------
// 2 blocks per window (32 tokens each). Stages the shifted-window tile
// token-major in smem, computes LN per token, writes BOTH g_xw (shortcut)
// and g_xn (LN1 output) coalesced.
#define S2_STR 196
__global__ __launch_bounds__(256) void gather_ln_kernel(const float* __restrict__ x,
                                                        const float* __restrict__ gam,
                                                        const float* __restrict__ bet) {
    __shared__ float s2[32 * S2_STR];
    __shared__ float sg[192], sb[192];
    __shared__ float smu[32], srs[32];
    int blk = blockIdx.x;            // (b*NW + n)*2 + half
    int half = blk & 1;
    int bn = blk >> 1;
    int b = bn / NW_;
    int n = bn % NW_;
    int wh = n >> 4, ww = n & 15;
    long tokbase = (long)bn * 64 + half * 32;
    int tid = threadIdx.x;

    for (int t = tid; t < 192; t += 256) { sg[t] = gam[t]; sb[t] = bet[t]; }

    #pragma unroll
    for (int ci = 0; ci < 4; ci++) {
        #pragma unroll
        for (int t = 0; t < 6; t++) {
            int idx = tid + t * 256;         // 0..1535
            int c = idx >> 5, l = idx & 31;  // c 0..47, l 0..31
            int hr = (wh * 8 + half * 4 + (l >> 3) + SHIFT_) & 127;
            int wc = (ww * 8 + (l & 7) + SHIFT_) & 127;
            s2[l * S2_STR + ci * 48 + c] = x[(((b * C_ + ci * 48 + c) * H_ + hr) << 7) + wc];
        }
    }
    __syncthreads();

    // LN: 8 threads per token
    int l = tid >> 3, part = tid & 7;
    float sum = 0.f;
    #pragma unroll
    for (int u = 0; u < 24; u++) sum += s2[l * S2_STR + part + 8 * u];
    sum += __shfl_xor_sync(0xffffffffu, sum, 1);
    sum += __shfl_xor_sync(0xffffffffu, sum, 2);
    sum += __shfl_xor_sync(0xffffffffu, sum, 4);
    float mu = sum * (1.0f / 192.0f);
    float sq = 0.f;
    #pragma unroll
    for (int u = 0; u < 24; u++) {
        float d = s2[l * S2_STR + part + 8 * u] - mu;
        sq += d * d;
    }
    sq += __shfl_xor_sync(0xffffffffu, sq, 1);
    sq += __shfl_xor_sync(0xffffffffu, sq, 2);
    sq += __shfl_xor_sync(0xffffffffu, sq, 4);
    float rstd = rsqrtf(sq * (1.0f / 192.0f) + 1e-5f);
    if (part == 0) { smu[l] = mu; srs[l] = rstd; }
    __syncthreads();

    for (int idx = tid; idx < 32 * 192; idx += 256) {
        int l2 = idx / 192, c = idx - l2 * 192;
        float v = s2[l2 * S2_STR + c];
        long off = (tokbase + l2) * C_ + c;
        g_xw[off] = v;
        g_xn[off] = (v - smu[l2]) * srs[l2] * sg[c] + sb[c];
    }
}

// ---------------- scatter: g_xn[T][C] --reverse window + roll(+4,+4)--> out -
__global__ __launch_bounds__(256) void scatter_kernel(float* __restrict__ out) {
    __shared__ float s[48 * 65];
    int blk = blockIdx.x;
    int b = blk / NW_;
    int n = blk % NW_;
    int wh = n >> 4, ww = n & 15;
    long tokbase = (long)blk * L_;
    int tid = threadIdx.x;
    for (int ci = 0; ci < 4; ci++) {
        #pragma unroll
        for (int t = 0; t < 12; t++) {
            int idx = tid + t * 256;
            int l = idx / 48, c = idx % 48;
            s[c * 65 + l] = g_xn[(tokbase + l) * C_ + ci * 48 + c];
        }
        __syncthreads();
        #pragma unroll
        for (int t = 0; t < 12; t++) {
            int idx = tid + t * 256;
            int c = idx >> 6, l = idx & 63;
            int hr = (wh * 8 + (l >> 3) + SHIFT_) & 127;
            int wc = (ww * 8 + (l & 7) + SHIFT_) & 127;
            out[(((b * C_ + ci * 48 + c) * H_ + hr) << 7) + wc] = s[c * 65 + l];
        }
        __syncthreads();
    }
}

// ---------------- layernorm (used for LN2): warp per token over C=192 -------
__global__ __launch_bounds__(256) void ln_sym(int selI, int selO,
                                              const float* __restrict__ gam,
                                              const float* __restrict__ bet) {
    const float* in = buf_ptr(selI);
    float* out = buf_ptr(selO);
    int warp = threadIdx.x >> 5;
    int lane = threadIdx.x & 31;
    long tok = (long)blockIdx.x * 8 + warp;
    const float* row = in + tok * C_;
    float v[6];
    float sum = 0.f;
    #pragma unroll
    for (int u = 0; u < 6; u++) { v[u] = row[lane + 32 * u]; sum += v[u]; }
    #pragma unroll
    for (int o = 16; o; o >>= 1) sum += __shfl_xor_sync(0xffffffffu, sum, o);
    float mu = sum * (1.0f / 192.0f);
    float sq = 0.f;
    #pragma unroll
    for (int u = 0; u < 6; u++) { float d = v[u] - mu; sq += d * d; }
    #pragma unroll
    for (int o = 16; o; o >>= 1) sq += __shfl_xor_sync(0xffffffffu, sq, o);
    float rstd = rsqrtf(sq * (1.0f / 192.0f) + 1e-5f);
    float* orow = out + tok * C_;
    #pragma unroll
    for (int u = 0; u < 6; u++) {
        int c = lane + 32 * u;
        orow[c] = (v[u] - mu) * rstd * gam[c] + bet[c];
    }
}

// ---------------- TF32 tensor-core GEMM, 128x96 tile, cp.async double-buffer
// A tile row-major [128][20] (conflict-free fragment loads), B tile [16][104]
// (104 ≡ 8 mod 32 -> conflict-free). Raw fp32 bits in smem; mma truncates.
enum { OP_BIAS = 0, OP_BIAS_RES = 1, OP_BIAS_GELU = 2 };

template<int OP>
__global__ __launch_bounds__(256) void tgemm_sym(int selA, int selR, int selO,
                                                 const float* __restrict__ Wm,
                                                 const float* __restrict__ bias,
                                                 int M, int N, int K) {
    const float* A = buf_ptr(selA);
    const float* R = buf_ptr(selR);
    float* O = buf_ptr(selO);

    __shared__ uint32_t As[2][128][20];
    __shared__ uint32_t Bs[2][16][104];

    int tid = threadIdx.x;
    int warp = tid >> 5;
    int lane = tid & 31;
    int gid = lane >> 2;               // 0..7
    int tig = lane & 3;                // 0..3
    int wm = (warp >> 1) * 32;         // 0,32,64,96
    int wn = (warp & 1) * 48;          // 0,48
    int m0 = blockIdx.y * 128;
    int n0 = blockIdx.x * 96;

    int a_row0 = tid >> 2, a_q = tid & 3;   // A chunks 0..255
    int a_row1 = a_row0 + 64;               // A chunks 256..511
    int b_row0 = tid / 24, b_q0 = tid % 24;             // B chunks 0..255
    int b_row1 = (tid + 256) / 24, b_q1 = (tid + 256) % 24;  // 256..383 (tid<128)

    float acc[2][6][4];
    #pragma unroll
    for (int i = 0; i < 2; i++)
        #pragma unroll
        for (int j = 0; j < 6; j++)
            #pragma unroll
            for (int c = 0; c < 4; c++) acc[i][j][c] = 0.f;

    const int NKC = K >> 4;

    // prefetch chunk 0 into buffer 0
    cp_async16(&As[0][a_row0][a_q * 4], A + (long)(m0 + a_row0) * K + a_q * 4);
    cp_async16(&As[0][a_row1][a_q * 4], A + (long)(m0 + a_row1) * K + a_q * 4);
    cp_async16(&Bs[0][b_row0][b_q0 * 4], Wm + (long)b_row0 * N + n0 + b_q0 * 4);
    if (tid < 128)
        cp_async16(&Bs[0][b_row1][b_q1 * 4], Wm + (long)b_row1 * N + n0 + b_q1 * 4);
    asm volatile("cp.async.commit_group;");

    int bf = 0;
    for (int it = 0; it < NKC; it++) {
        if (it + 1 < NKC) {
            int kk = (it + 1) << 4;
            int nb = bf ^ 1;
            cp_async16(&As[nb][a_row0][a_q * 4], A + (long)(m0 + a_row0) * K + kk + a_q * 4);
            cp_async16(&As[nb][a_row1][a_q * 4], A + (long)(m0 + a_row1) * K + kk + a_q * 4);
            cp_async16(&Bs[nb][b_row0][b_q0 * 4], Wm + (long)(kk + b_row0) * N + n0 + b_q0 * 4);
            if (tid < 128)
                cp_async16(&Bs[nb][b_row1][b_q1 * 4], Wm + (long)(kk + b_row1) * N + n0 + b_q1 * 4);
            asm volatile("cp.async.commit_group;");
            asm volatile("cp.async.wait_group 1;");
        } else {
            asm volatile("cp.async.wait_group 0;");
        }
        __syncthreads();

        #pragma unroll
        for (int ks = 0; ks < 2; ks++) {
            int kb = ks * 8;
            uint32_t a[2][4], b[6][2];
            #pragma unroll
            for (int mi = 0; mi < 2; mi++) {
                int mrow = wm + mi * 16 + gid;
                a[mi][0] = As[bf][mrow][kb + tig];
                a[mi][1] = As[bf][mrow + 8][kb + tig];
                a[mi][2] = As[bf][mrow][kb + tig + 4];
                a[mi][3] = As[bf][mrow + 8][kb + tig + 4];
            }
            #pragma unroll
            for (int ni = 0; ni < 6; ni++) {
                int ncol = wn + ni * 8 + gid;
                b[ni][0] = Bs[bf][kb + tig][ncol];
                b[ni][1] = Bs[bf][kb + tig + 4][ncol];
            }
            #pragma unroll
            for (int mi = 0; mi < 2; mi++)
                #pragma unroll
                for (int ni = 0; ni < 6; ni++)
                    mma_tf32(acc[mi][ni], a[mi], b[ni]);
        }
        bf ^= 1;
        __syncthreads();
    }

    #pragma unroll
    for (int mi = 0; mi < 2; mi++) {
        #pragma unroll
        for (int ni = 0; ni < 6; ni++) {
            int col = n0 + wn + ni * 8 + tig * 2;
            float bv0 = bias[col], bv1 = bias[col + 1];
            #pragma unroll
            for (int h = 0; h < 2; h++) {
                long row = m0 + wm + mi * 16 + gid + h * 8;
                float v0 = acc[mi][ni][h * 2 + 0] + bv0;
                float v1 = acc[mi][ni][h * 2 + 1] + bv1;
                if (OP == OP_BIAS_GELU) {
                    v0 = 0.5f * v0 * (1.0f + erff(v0 * 0.70710678118654752f));
                    v1 = 0.5f * v1 * (1.0f + erff(v1 * 0.70710678118654752f));
                }
                if (OP == OP_BIAS_RES) {
                    v0 += R[row * N + col];
                    v1 += R[row * N + col + 1];
                }
                float2 o = make_float2(v0, v1);
                *(float2*)(O + row * N + col) = o;
            }
        }
    }
}

// ---------------- tensor-core windowed attention ----------------------------
// one 128-thread block per (b, window, head); 4 warps, 16 rows each
#define QK_STR 72   // ≡ 8 mod 32 -> conflict-free B/A fragment loads
#define V_STR  56   // ≡ 24 mod 32 -> conflict-free
#define P_STR  68   // ≡ 4 mod 32 -> conflict-free A fragment loads

__global__ __launch_bounds__(128) void attn_mma_kernel(const float* __restrict__ bias_table) {
    __shared__ uint32_t sQK[2 * 48 * QK_STR];   // Q at 0, K at 3456; reused as P
    __shared__ uint32_t sV[64 * V_STR];
    __shared__ float bb[225];

    uint32_t* sQ = sQK;
    uint32_t* sK = sQK + 48 * QK_STR;
    uint32_t* sP = sQK;

    int blk = blockIdx.x;            // (b*NW + n)*HEADS + head
    int head = blk & 3;
    int bn = blk >> 2;
    int n = bn % NW_;
    int wh = n >> 4, ww = n & 15;
    long tokbase = (long)bn * 64;
    int tid = threadIdx.x;
    int warp = tid >> 5;
    int lane = tid & 31;
    int gid = lane >> 2;             // 0..7
    int tig = lane & 3;              // 0..3

    for (int t = tid; t < 225; t += 128) bb[t] = bias_table[head * 225 + t];

    const float scale = 0.14433756729740643f;   // 1/sqrt(48)
    for (int t = tid; t < 768; t += 128) {       // 64 rows x 12 float4
        int l = t / 12, q4 = t % 12, d = q4 * 4;
        const float* base = g_big + (tokbase + l) * 576 + head * 48 + d;
        float4 q = *(const float4*)(base);
        float4 k = *(const float4*)(base + 192);
        float4 v = *(const float4*)(base + 384);
        sQ[(d + 0) * QK_STR + l] = to_tf32(q.x * scale);
        sQ[(d + 1) * QK_STR + l] = to_tf32(q.y * scale);
        sQ[(d + 2) * QK_STR + l] = to_tf32(q.z * scale);
        sQ[(d + 3) * QK_STR + l] = to_tf32(q.w * scale);
        sK[(d + 0) * QK_STR + l] = to_tf32(k.x);
        sK[(d + 1) * QK_STR + l] = to_tf32(k.y);
        sK[(d + 2) * QK_STR + l] = to_tf32(k.z);
        sK[(d + 3) * QK_STR + l] = to_tf32(k.w);
        uint4 vv = make_uint4(to_tf32(v.x), to_tf32(v.y), to_tf32(v.z), to_tf32(v.w));
        *(uint4*)&sV[l * V_STR + d] = vv;
    }
    __syncthreads();

    int r0 = warp * 16 + gid;
    float acc[8][4];
    #pragma unroll
    for (int ni = 0; ni < 8; ni++)
        #pragma unroll
        for (int c = 0; c < 4; c++) acc[ni][c] = 0.f;

    #pragma unroll
    for (int kb = 0; kb < 6; kb++) {
        int k = kb * 8;
        uint32_t a[4];
        a[0] = sQ[(k + tig) * QK_STR + r0];
        a[1] = sQ[(k + tig) * QK_STR + r0 + 8];
        a[2] = sQ[(k + tig + 4) * QK_STR + r0];
        a[3] = sQ[(k + tig + 4) * QK_STR + r0 + 8];
        #pragma unroll
        for (int ni = 0; ni < 8; ni++) {
            uint32_t b[2];
            b[0] = sK[(k + tig) * QK_STR + ni * 8 + gid];
            b[1] = sK[(k + tig + 4) * QK_STR + ni * 8 + gid];
            mma_tf32(acc[ni], a, b);
        }
    }

    int ih0 = r0 >> 3, iw0 = r0 & 7;
    int r1 = r0 + 8;
    int ih1 = r1 >> 3, iw1 = r1 & 7;
    int reg_i0 = ((wh == 15) ? (ih0 < 4 ? 3 : 6) : 0) + ((ww == 15) ? (iw0 < 4 ? 1 : 2) : 0);
    int reg_i1 = ((wh == 15) ? (ih1 < 4 ? 3 : 6) : 0) + ((ww == 15) ? (iw1 < 4 ? 1 : 2) : 0);

    float mx0 = -1e30f, mx1 = -1e30f;
    #pragma unroll
    for (int ni = 0; ni < 8; ni++) {
        #pragma unroll
        for (int hh = 0; hh < 2; hh++) {
            int j = ni * 8 + tig * 2 + hh;
            int jh = j >> 3, jw = j & 7;
            int reg_j = ((wh == 15) ? (jh < 4 ? 3 : 6) : 0) + ((ww == 15) ? (jw < 4 ? 1 : 2) : 0);
            float bt0 = (reg_i0 != reg_j) ? -100.0f : bb[(ih0 - jh + 7) * 15 + (iw0 - jw + 7)];
            float bt1 = (reg_i1 != reg_j) ? -100.0f : bb[(ih1 - jh + 7) * 15 + (iw1 - jw + 7)];
            acc[ni][hh]     += bt0;
            acc[ni][2 + hh] += bt1;
            mx0 = fmaxf(mx0, acc[ni][hh]);
            mx1 = fmaxf(mx1, acc[ni][2 + hh]);
        }
    }
    mx0 = fmaxf(mx0, __shfl_xor_sync(0xffffffffu, mx0, 1));
    mx0 = fmaxf(mx0, __shfl_xor_sync(0xffffffffu, mx0, 2));
    mx1 = fmaxf(mx1, __shfl_xor_sync(0xffffffffu, mx1, 1));
    mx1 = fmaxf(mx1, __shfl_xor_sync(0xffffffffu, mx1, 2));
    float s0 = 0.f, s1 = 0.f;
    #pragma unroll
    for (int ni = 0; ni < 8; ni++) {
        #pragma unroll
        for (int hh = 0; hh < 2; hh++) {
            acc[ni][hh]     = __expf(acc[ni][hh] - mx0);     s0 += acc[ni][hh];
            acc[ni][2 + hh] = __expf(acc[ni][2 + hh] - mx1); s1 += acc[ni][2 + hh];
        }
    }
    s0 += __shfl_xor_sync(0xffffffffu, s0, 1);
    s0 += __shfl_xor_sync(0xffffffffu, s0, 2);
    s1 += __shfl_xor_sync(0xffffffffu, s1, 1);
    s1 += __shfl_xor_sync(0xffffffffu, s1, 2);
    float inv0 = 1.0f / s0, inv1 = 1.0f / s1;

    __syncthreads();

    #pragma unroll
    for (int ni = 0; ni < 8; ni++) {
        int j = ni * 8 + tig * 2;
        sP[r0 * P_STR + j]     = to_tf32(acc[ni][0] * inv0);
        sP[r0 * P_STR + j + 1] = to_tf32(acc[ni][1] * inv0);
        sP[r1 * P_STR + j]     = to_tf32(acc[ni][2] * inv1);
        sP[r1 * P_STR + j + 1] = to_tf32(acc[ni][3] * inv1);
    }
    __syncthreads();

    float oacc[6][4];
    #pragma unroll
    for (int ni = 0; ni < 6; ni++)
        #pragma unroll
        for (int c = 0; c < 4; c++) oacc[ni][c] = 0.f;

    #pragma unroll
    for (int kt = 0; kt < 8; kt++) {
        int k = kt * 8;
        uint32_t a[4];
        a[0] = sP[r0 * P_STR + k + tig];
        a[1] = sP[r1 * P_STR + k + tig];
        a[2] = sP[r0 * P_STR + k + tig + 4];
        a[3] = sP[r1 * P_STR + k + tig + 4];
        #pragma unroll
        for (int ni = 0; ni < 6; ni++) {
            uint32_t b[2];
            b[0] = sV[(k + tig) * V_STR + ni * 8 + gid];
            b[1] = sV[(k + tig + 4) * V_STR + ni * 8 + gid];
            mma_tf32(oacc[ni], a, b);
        }
    }

    #pragma unroll
    for (int ni = 0; ni < 6; ni++) {
        int col = ni * 8 + tig * 2;
        float* p0 = g_xn + (tokbase + r0) * C_ + head * 48 + col;
        float* p1 = g_xn + (tokbase + r1) * C_ + head * 48 + col;
        *(float2*)p0 = make_float2(oacc[ni][0], oacc[ni][1]);
        *(float2*)p1 = make_float2(oacc[ni][2], oacc[ni][3]);
    }
}

// ---------------- launcher ---------------------------------------------------
extern "C" void kernel_launch(void* const* d_in, const int* in_sizes, int n_in,
                              void* d_out, int out_size) {
    const float* x   = (const float*)d_in[0];
    const float* bt  = (const float*)d_in[1];
    const float* qw  = (const float*)d_in[2];
    const float* qb  = (const float*)d_in[3];
    const float* pw  = (const float*)d_in[4];
    const float* pb  = (const float*)d_in[5];
    const float* g1  = (const float*)d_in[6];
    const float* b1  = (const float*)d_in[7];
    const float* g2  = (const float*)d_in[8];
    const float* b2  = (const float*)d_in[9];
    const float* w1  = (const float*)d_in[10];
    const float* bb1 = (const float*)d_in[11];
    const float* w2  = (const float*)d_in[12];
    const float* bb2 = (const float*)d_in[13];
    float* out = (float*)d_out;

    // 1+2. shifted window partition + LN1 fused  (x -> g_xw, g_xn)
    gather_ln_kernel<<<B_ * NW_ * 2, 256>>>(x, g1, b1);
    // 3. QKV GEMM: [T,192] @ [192,576]  (g_xn -> g_big)
    tgemm_sym<OP_BIAS><<<dim3(576 / 96, T_ / 128), 256>>>(BUF_XN, BUF_XN, BUF_BIG, qw, qb, T_, 576, 192);
    // 4. tensor-core windowed attention (g_big -> g_xn, head-major C)
    attn_mma_kernel<<<B_ * NW_ * HEADS_, 128>>>(bt);
    // 5. proj GEMM + residual (g_xn @ pw + g_xw -> g_x1)
    tgemm_sym<OP_BIAS_RES><<<dim3(192 / 96, T_ / 128), 256>>>(BUF_XN, BUF_XW, BUF_X1, pw, pb, T_, 192, 192);
    // 6. LN2 (g_x1 -> g_xw)
    ln_sym<<<T_ / 8, 256>>>(BUF_X1, BUF_XW, g2, b2);
    // 7. MLP1 + exact GELU: [T,192] @ [192,768]  (g_xw -> g_big)
    tgemm_sym<OP_BIAS_GELU><<<dim3(768 / 96, T_ / 128), 256>>>(BUF_XW, BUF_XW, BUF_BIG, w1, bb1, T_, 768, 192);
    // 8. MLP2 + residual: [T,768] @ [768,192] + g_x1 -> g_xn
    tgemm_sym<OP_BIAS_RES><<<dim3(192 / 96, T_ / 128), 256>>>(BUF_BIG, BUF_X1, BUF_XN, w2, bb2, T_, 192, 768);
    // 9. window reverse + roll(+4,+4)  (g_xn -> out)
    scatter_kernel<<<B_ * NW_, 256>>>(out);
}

// round 12
// speedup vs baseline: 1.8460x; 1.2811x over previous
#include <cuda_runtime.h>
#include <cuda_bf16.h>
#include <math.h>
#include <stdint.h>

// ---------------- static config ----------------
#define B_     8
#define C_     192
#define H_     128
#define W_     128
#define WS_    8
#define SHIFT_ 4
#define HEADS_ 4
#define HD_    48
#define L_     64
#define NW_    256
#define T_     (B_*NW_*L_)         // 131072 tokens
#define HID_   768

// ---------------- scratch (static device globals) ---------------------------
// NOTE: x2 (pre-scatter output) is stored in the first T*192 columns of g_big,
// which is free after attention has consumed the qkv tensor (launches are
// strictly serialized on one stream). Keeps total static footprint ~755 MB.
__device__ float g_xw [(size_t)T_ * C_];      // shortcut (fp32)
__device__ float g_x1 [(size_t)T_ * C_];      // residual-1 (fp32)
__device__ float g_big[(size_t)T_ * 576];     // qkv (fp32) -> later x2 [T][192]
__device__ __nv_bfloat16 g_a0 [(size_t)T_ * C_];    // bf16 activations (LN1/attnout/LN2)
__device__ __nv_bfloat16 g_hid[(size_t)T_ * HID_];  // bf16 mlp hidden
// bf16 transposed weights [N][K]
__device__ __nv_bfloat16 g_wqkv[576 * 192];
__device__ __nv_bfloat16 g_wproj[192 * 192];
__device__ __nv_bfloat16 g_w1[768 * 192];
__device__ __nv_bfloat16 g_w2[192 * 768];

enum FBuf { FB_XW = 0, FB_X1 = 1, FB_BIG = 2 };
enum ABuf { AB_A0 = 0, AB_HID = 1 };
enum WBuf { WB_QKV = 0, WB_PROJ = 1, WB_W1 = 2, WB_W2 = 3 };

__device__ __forceinline__ float* fbuf_ptr(int sel) {
    switch (sel) {
        case FB_XW: return g_xw;
        case FB_X1: return g_x1;
        default:    return g_big;
    }
}
__device__ __forceinline__ __nv_bfloat16* abuf_ptr(int sel) {
    return sel == AB_A0 ? g_a0 : g_hid;
}
__device__ __forceinline__ __nv_bfloat16* wbuf_ptr(int sel) {
    switch (sel) {
        case WB_QKV:  return g_wqkv;
        case WB_PROJ: return g_wproj;
        case WB_W1:   return g_w1;
        default:      return g_w2;
    }
}

__device__ __forceinline__ uint32_t to_tf32(float f) {
    uint32_t r;
    asm("cvt.rna.tf32.f32 %0, %1;" : "=r"(r) : "f"(f));
    return r;
}

__device__ __forceinline__ void mma_tf32(float c[4],
                                         const uint32_t a[4], const uint32_t b[2]) {
    asm volatile(
        "mma.sync.aligned.m16n8k8.row.col.f32.tf32.tf32.f32 "
        "{%0,%1,%2,%3}, {%4,%5,%6,%7}, {%8,%9}, {%0,%1,%2,%3};"
        : "+f"(c[0]), "+f"(c[1]), "+f"(c[2]), "+f"(c[3])
        : "r"(a[0]), "r"(a[1]), "r"(a[2]), "r"(a[3]), "r"(b[0]), "r"(b[1]));
}

__device__ __forceinline__ void mma_bf16(float c[4],
                                         const uint32_t a[4], const uint32_t b[2]) {
    asm volatile(
        "mma.sync.aligned.m16n8k16.row.col.f32.bf16.bf16.f32 "
        "{%0,%1,%2,%3}, {%4,%5,%6,%7}, {%8,%9}, {%0,%1,%2,%3};"
        : "+f"(c[0]), "+f"(c[1]), "+f"(c[2]), "+f"(c[3])
        : "r"(a[0]), "r"(a[1]), "r"(a[2]), "r"(a[3]), "r"(b[0]), "r"(b[1]));
}

__device__ __forceinline__ void cp_async16(void* smem, const void* gmem) {
    uint32_t s = (uint32_t)__cvta_generic_to_shared(smem);
    asm volatile("cp.async.ca.shared.global [%0], [%1], 16;" :: "r"(s), "l"(gmem));
}

// ---------------- weight convert + transpose: fp32[K][N] -> bf16[N][K] ------
__global__ __launch_bounds__(256) void convert_w_kernel(int selW, const float* __restrict__ src,
                                                        int K, int N) {
    __nv_bfloat16* dst = wbuf_ptr(selW);
    int i = blockIdx.x * 256 + threadIdx.x;
    if (i < K * N) {
        int n = i / K, k = i - n * K;
        dst[i] = __float2bfloat16(src[(long)k * N + n]);
    }
}

// ---------------- fused gather + LN1: x -> g_xw (fp32) + g_a0 (bf16) --------
#define S2_STR 196
__global__ __launch_bounds__(256) void gather_ln_kernel(const float* __restrict__ x,
                                                        const float* __restrict__ gam,
                                                        const float* __restrict__ bet) {
    __shared__ float s2[32 * S2_STR];
    __shared__ float sg[192], sb[192];
    __shared__ float smu[32], srs[32];
    int blk = blockIdx.x;
    int half = blk & 1;
    int bn = blk >> 1;
    int b = bn / NW_;
    int n = bn % NW_;
    int wh = n >> 4, ww = n & 15;
    long tokbase = (long)bn * 64 + half * 32;
    int tid = threadIdx.x;

    for (int t = tid; t < 192; t += 256) { sg[t] = gam[t]; sb[t] = bet[t]; }

    #pragma unroll
    for (int ci = 0; ci < 4; ci++) {
        #pragma unroll
        for (int t = 0; t < 6; t++) {
            int idx = tid + t * 256;
            int c = idx >> 5, l = idx & 31;
            int hr = (wh * 8 + half * 4 + (l >> 3) + SHIFT_) & 127;
            int wc = (ww * 8 + (l & 7) + SHIFT_) & 127;
            s2[l * S2_STR + ci * 48 + c] = x[(((b * C_ + ci * 48 + c) * H_ + hr) << 7) + wc];
        }
    }
    __syncthreads();

    int l = tid >> 3, part = tid & 7;
    float sum = 0.f;
    #pragma unroll
    for (int u = 0; u < 24; u++) sum += s2[l * S2_STR + part + 8 * u];
    sum += __shfl_xor_sync(0xffffffffu, sum, 1);
    sum += __shfl_xor_sync(0xffffffffu, sum, 2);
    sum += __shfl_xor_sync(0xffffffffu, sum, 4);
    float mu = sum * (1.0f / 192.0f);
    float sq = 0.f;
    #pragma unroll
    for (int u = 0; u < 24; u++) {
        float d = s2[l * S2_STR + part + 8 * u] - mu;
        sq += d * d;
    }
    sq += __shfl_xor_sync(0xffffffffu, sq, 1);
    sq += __shfl_xor_sync(0xffffffffu, sq, 2);
    sq += __shfl_xor_sync(0xffffffffu, sq, 4);
    float rstd = rsqrtf(sq * (1.0f / 192.0f) + 1e-5f);
    if (part == 0) { smu[l] = mu; srs[l] = rstd; }
    __syncthreads();

    for (int idx = tid; idx < 32 * 192; idx += 256) {
        int l2 = idx / 192, c = idx - l2 * 192;
        float v = s2[l2 * S2_STR + c];
        long off = (tokbase + l2) * C_ + c;
        g_xw[off] = v;
        g_a0[off] = __float2bfloat16((v - smu[l2]) * srs[l2] * sg[c] + sb[c]);
    }
}

// ---------------- LN2: g_x1 (fp32) -> g_a0 (bf16) ---------------------------
__global__ __launch_bounds__(256) void ln2_kernel(const float* __restrict__ gam,
                                                  const float* __restrict__ bet) {
    int warp = threadIdx.x >> 5;
    int lane = threadIdx.x & 31;
    long tok = (long)blockIdx.x * 8 + warp;
    const float* row = g_x1 + tok * C_;
    float v[6];
    float sum = 0.f;
    #pragma unroll
    for (int u = 0; u < 6; u++) { v[u] = row[lane + 32 * u]; sum += v[u]; }
    #pragma unroll
    for (int o = 16; o; o >>= 1) sum += __shfl_xor_sync(0xffffffffu, sum, o);
    float mu = sum * (1.0f / 192.0f);
    float sq = 0.f;
    #pragma unroll
    for (int u = 0; u < 6; u++) { float d = v[u] - mu; sq += d * d; }
    #pragma unroll
    for (int o = 16; o; o >>= 1) sq += __shfl_xor_sync(0xffffffffu, sq, o);
    float rstd = rsqrtf(sq * (1.0f / 192.0f) + 1e-5f);
    __nv_bfloat16* orow = g_a0 + tok * C_;
    #pragma unroll
    for (int u = 0; u < 6; u++) {
        int c = lane + 32 * u;
        orow[c] = __float2bfloat16((v[u] - mu) * rstd * gam[c] + bet[c]);
    }
}

// ---------------- scatter: g_big[T][192] (x2) -> out (reverse window + roll)
__global__ __launch_bounds__(256) void scatter_kernel(float* __restrict__ out) {
    __shared__ float s[48 * 65];
    int blk = blockIdx.x;
    int b = blk / NW_;
    int n = blk % NW_;
    int wh = n >> 4, ww = n & 15;
    long tokbase = (long)blk * L_;
    int tid = threadIdx.x;
    for (int ci = 0; ci < 4; ci++) {
        #pragma unroll
        for (int t = 0; t < 12; t++) {
            int idx = tid + t * 256;
            int l = idx / 48, c = idx % 48;
            s[c * 65 + l] = g_big[(tokbase + l) * C_ + ci * 48 + c];
        }
        __syncthreads();
        #pragma unroll
        for (int t = 0; t < 12; t++) {
            int idx = tid + t * 256;
            int c = idx >> 6, l = idx & 63;
            int hr = (wh * 8 + (l >> 3) + SHIFT_) & 127;
            int wc = (ww * 8 + (l & 7) + SHIFT_) & 127;
            out[(((b * C_ + ci * 48 + c) * H_ + hr) << 7) + wc] = s[c * 65 + l];
        }
        __syncthreads();
    }
}

// ---------------- bf16 tensor-core GEMM -------------------------------------
// O[M,N] = A[M,K](bf16) @ Wt[N,K]^T(bf16) + bias (+gelu->bf16 / +res->fp32)
// 128x96 block tile, 8 warps (4m x 2n), warp 32x48, k-chunk 16, one mma k-step.
// Smem tiles stored as u32 (2 halves each), row stride 12 u32 (=24 halves):
// fragment loads 12*gid+tig are a permutation mod 32 -> conflict-free.
enum { OP_BIAS = 0, OP_BIAS_RES = 1, OP_BIAS_GELU = 2 };

template<int OP, int K>
__global__ __launch_bounds__(256) void tgemm_bf16(int selA, int selR, int selO,
                                                  int selW,
                                                  const float* __restrict__ bias,
                                                  int M, int N) {
    const __nv_bfloat16* A = abuf_ptr(selA);
    const __nv_bfloat16* Wt = wbuf_ptr(selW);
    const float* R = fbuf_ptr(selR);

    __shared__ uint32_t As[2][128][12];   // 24 halves/row (16 data + 8 pad)
    __shared__ uint32_t Bs[2][96][12];

    int tid = threadIdx.x;
    int warp = tid >> 5;
    int lane = tid & 31;
    int gid = lane >> 2;
    int tig = lane & 3;
    int wm = (warp >> 1) * 32;
    int wn = (warp & 1) * 48;
    int m0 = blockIdx.y * 128;
    int n0 = blockIdx.x * 96;

    int a_row = tid >> 1, a_h = tid & 1;            // 128 rows x 2 halves-of-16B
    int b_row = tid >> 1, b_h = tid & 1;            // 96 rows (tid < 192)

    float acc[2][6][4];
    #pragma unroll
    for (int i = 0; i < 2; i++)
        #pragma unroll
        for (int j = 0; j < 6; j++)
            #pragma unroll
            for (int c = 0; c < 4; c++) acc[i][j][c] = 0.f;

    const int NKC = K >> 4;

    // prefetch chunk 0 -> stage 0
    cp_async16((char*)&As[0][a_row][0] + a_h * 16, A + (long)(m0 + a_row) * K + a_h * 8);
    if (tid < 192)
        cp_async16((char*)&Bs[0][b_row][0] + b_h * 16, Wt + (long)(n0 + b_row) * K + b_h * 8);
    asm volatile("cp.async.commit_group;");

    int bf = 0;
    for (int it = 0; it < NKC; it++) {
        asm volatile("cp.async.wait_group 0;");
        __syncthreads();
        if (it + 1 < NKC) {
            int kk = (it + 1) << 4;
            int nb = bf ^ 1;
            cp_async16((char*)&As[nb][a_row][0] + a_h * 16,
                       A + (long)(m0 + a_row) * K + kk + a_h * 8);
            if (tid < 192)
                cp_async16((char*)&Bs[nb][b_row][0] + b_h * 16,
                           Wt + (long)(n0 + b_row) * K + kk + b_h * 8);
            asm volatile("cp.async.commit_group;");
        }

        uint32_t a[2][4], b[6][2];
        #pragma unroll
        for (int mi = 0; mi < 2; mi++) {
            int mrow = wm + mi * 16 + gid;
            a[mi][0] = As[bf][mrow][tig];
            a[mi][1] = As[bf][mrow + 8][tig];
            a[mi][2] = As[bf][mrow][tig + 4];
            a[mi][3] = As[bf][mrow + 8][tig + 4];
        }
        #pragma unroll
        for (int ni = 0; ni < 6; ni++) {
            int ncol = wn + ni * 8 + gid;
            b[ni][0] = Bs[bf][ncol][tig];
            b[ni][1] = Bs[bf][ncol][tig + 4];
        }
        #pragma unroll
        for (int mi = 0; mi < 2; mi++)
            #pragma unroll
            for (int ni = 0; ni < 6; ni++)
                mma_bf16(acc[mi][ni], a[mi], b[ni]);

        bf ^= 1;
    }

    // epilogue
    #pragma unroll
    for (int mi = 0; mi < 2; mi++) {
        #pragma unroll
        for (int ni = 0; ni < 6; ni++) {
            int col = n0 + wn + ni * 8 + tig * 2;
            float bv0 = bias[col], bv1 = bias[col + 1];
            #pragma unroll
            for (int h = 0; h < 2; h++) {
                long row = m0 + wm + mi * 16 + gid + h * 8;
                float v0 = acc[mi][ni][h * 2 + 0] + bv0;
                float v1 = acc[mi][ni][h * 2 + 1] + bv1;
                if (OP == OP_BIAS_GELU) {
                    v0 = 0.5f * v0 * (1.0f + erff(v0 * 0.70710678118654752f));
                    v1 = 0.5f * v1 * (1.0f + erff(v1 * 0.70710678118654752f));
                    __nv_bfloat16* Oh = abuf_ptr(selO);
                    __nv_bfloat162 p;
                    p.x = __float2bfloat16(v0);
                    p.y = __float2bfloat16(v1);
                    *(__nv_bfloat162*)(Oh + row * N + col) = p;
                } else {
                    if (OP == OP_BIAS_RES) {
                        v0 += R[row * N + col];
                        v1 += R[row * N + col + 1];
                    }
                    float* Of = fbuf_ptr(selO);
                    *(float2*)(Of + row * N + col) = make_float2(v0, v1);
                }
            }
        }
    }
}

// ---------------- tensor-core windowed attention (tf32) ---------------------
// Reads qkv fp32 from g_big; writes output bf16 into g_a0.
#define QK_STR 72
#define V_STR  56
#define P_STR  68

__global__ __launch_bounds__(128) void attn_mma_kernel(const float* __restrict__ bias_table) {
    __shared__ uint32_t sQK[2 * 48 * QK_STR];
    __shared__ uint32_t sV[64 * V_STR];
    __shared__ float bb[225];

    uint32_t* sQ = sQK;
    uint32_t* sK = sQK + 48 * QK_STR;
    uint32_t* sP = sQK;

    int blk = blockIdx.x;
    int head = blk & 3;
    int bn = blk >> 2;
    int n = bn % NW_;
    int wh = n >> 4, ww = n & 15;
    long tokbase = (long)bn * 64;
    int tid = threadIdx.x;
    int warp = tid >> 5;
    int lane = tid & 31;
    int gid = lane >> 2;
    int tig = lane & 3;

    for (int t = tid; t < 225; t += 128) bb[t] = bias_table[head * 225 + t];

    const float scale = 0.14433756729740643f;
    for (int t = tid; t < 768; t += 128) {
        int l = t / 12, q4 = t % 12, d = q4 * 4;
        const float* base = g_big + (tokbase + l) * 576 + head * 48 + d;
        float4 q = *(const float4*)(base);
        float4 k = *(const float4*)(base + 192);
        float4 v = *(const float4*)(base + 384);
        sQ[(d + 0) * QK_STR + l] = to_tf32(q.x * scale);
        sQ[(d + 1) * QK_STR + l] = to_tf32(q.y * scale);
        sQ[(d + 2) * QK_STR + l] = to_tf32(q.z * scale);
        sQ[(d + 3) * QK_STR + l] = to_tf32(q.w * scale);
        sK[(d + 0) * QK_STR + l] = to_tf32(k.x);
        sK[(d + 1) * QK_STR + l] = to_tf32(k.y);
        sK[(d + 2) * QK_STR + l] = to_tf32(k.z);
        sK[(d + 3) * QK_STR + l] = to_tf32(k.w);
        uint4 vv = make_uint4(to_tf32(v.x), to_tf32(v.y), to_tf32(v.z), to_tf32(v.w));
        *(uint4*)&sV[l * V_STR + d] = vv;
    }
    __syncthreads();

    int r0 = warp * 16 + gid;
    float acc[8][4];
    #pragma unroll
    for (int ni = 0; ni < 8; ni++)
        #pragma unroll
        for (int c = 0; c < 4; c++) acc[ni][c] = 0.f;

    #pragma unroll
    for (int kb = 0; kb < 6; kb++) {
        int k = kb * 8;
        uint32_t a[4];
        a[0] = sQ[(k + tig) * QK_STR + r0];
        a[1] = sQ[(k + tig) * QK_STR + r0 + 8];
        a[2] = sQ[(k + tig + 4) * QK_STR + r0];
        a[3] = sQ[(k + tig + 4) * QK_STR + r0 + 8];
        #pragma unroll
        for (int ni = 0; ni < 8; ni++) {
            uint32_t b[2];
            b[0] = sK[(k + tig) * QK_STR + ni * 8 + gid];
            b[1] = sK[(k + tig + 4) * QK_STR + ni * 8 + gid];
            mma_tf32(acc[ni], a, b);
        }
    }

    int ih0 = r0 >> 3, iw0 = r0 & 7;
    int r1 = r0 + 8;
    int ih1 = r1 >> 3, iw1 = r1 & 7;
    int reg_i0 = ((wh == 15) ? (ih0 < 4 ? 3 : 6) : 0) + ((ww == 15) ? (iw0 < 4 ? 1 : 2) : 0);
    int reg_i1 = ((wh == 15) ? (ih1 < 4 ? 3 : 6) : 0) + ((ww == 15) ? (iw1 < 4 ? 1 : 2) : 0);

    float mx0 = -1e30f, mx1 = -1e30f;
    #pragma unroll
    for (int ni = 0; ni < 8; ni++) {
        #pragma unroll
        for (int hh = 0; hh < 2; hh++) {
            int j = ni * 8 + tig * 2 + hh;
            int jh = j >> 3, jw = j & 7;
            int reg_j = ((wh == 15) ? (jh < 4 ? 3 : 6) : 0) + ((ww == 15) ? (jw < 4 ? 1 : 2) : 0);
            float bt0 = (reg_i0 != reg_j) ? -100.0f : bb[(ih0 - jh + 7) * 15 + (iw0 - jw + 7)];
            float bt1 = (reg_i1 != reg_j) ? -100.0f : bb[(ih1 - jh + 7) * 15 + (iw1 - jw + 7)];
            acc[ni][hh]     += bt0;
            acc[ni][2 + hh] += bt1;
            mx0 = fmaxf(mx0, acc[ni][hh]);
            mx1 = fmaxf(mx1, acc[ni][2 + hh]);
        }
    }
    mx0 = fmaxf(mx0, __shfl_xor_sync(0xffffffffu, mx0, 1));
    mx0 = fmaxf(mx0, __shfl_xor_sync(0xffffffffu, mx0, 2));
    mx1 = fmaxf(mx1, __shfl_xor_sync(0xffffffffu, mx1, 1));
    mx1 = fmaxf(mx1, __shfl_xor_sync(0xffffffffu, mx1, 2));
    float s0 = 0.f, s1 = 0.f;
    #pragma unroll
    for (int ni = 0; ni < 8; ni++) {
        #pragma unroll
        for (int hh = 0; hh < 2; hh++) {
            acc[ni][hh]     = __expf(acc[ni][hh] - mx0);     s0 += acc[ni][hh];
            acc[ni][2 + hh] = __expf(acc[ni][2 + hh] - mx1); s1 += acc[ni][2 + hh];
        }
    }
    s0 += __shfl_xor_sync(0xffffffffu, s0, 1);
    s0 += __shfl_xor_sync(0xffffffffu, s0, 2);
    s1 += __shfl_xor_sync(0xffffffffu, s1, 1);
    s1 += __shfl_xor_sync(0xffffffffu, s1, 2);
    float inv0 = 1.0f / s0, inv1 = 1.0f / s1;

    __syncthreads();

    #pragma unroll
    for (int ni = 0; ni < 8; ni++) {
        int j = ni * 8 + tig * 2;
        sP[r0 * P_STR + j]     = to_tf32(acc[ni][0] * inv0);
        sP[r0 * P_STR + j + 1] = to_tf32(acc[ni][1] * inv0);
        sP[r1 * P_STR + j]     = to_tf32(acc[ni][2] * inv1);
        sP[r1 * P_STR + j + 1] = to_tf32(acc[ni][3] * inv1);
    }
    __syncthreads();

    float oacc[6][4];
    #pragma unroll
    for (int ni = 0; ni < 6; ni++)
        #pragma unroll
        for (int c = 0; c < 4; c++) oacc[ni][c] = 0.f;

    #pragma unroll
    for (int kt = 0; kt < 8; kt++) {
        int k = kt * 8;
        uint32_t a[4];
        a[0] = sP[r0 * P_STR + k + tig];
        a[1] = sP[r1 * P_STR + k + tig];
        a[2] = sP[r0 * P_STR + k + tig + 4];
        a[3] = sP[r1 * P_STR + k + tig + 4];
        #pragma unroll
        for (int ni = 0; ni < 6; ni++) {
            uint32_t b[2];
            b[0] = sV[(k + tig) * V_STR + ni * 8 + gid];
            b[1] = sV[(k + tig + 4) * V_STR + ni * 8 + gid];
            mma_tf32(oacc[ni], a, b);
        }
    }

    #pragma unroll
    for (int ni = 0; ni < 6; ni++) {
        int col = ni * 8 + tig * 2;
        __nv_bfloat16* p0 = g_a0 + (tokbase + r0) * C_ + head * 48 + col;
        __nv_bfloat16* p1 = g_a0 + (tokbase + r1) * C_ + head * 48 + col;
        __nv_bfloat162 o0, o1;
        o0.x = __float2bfloat16(oacc[ni][0]); o0.y = __float2bfloat16(oacc[ni][1]);
        o1.x = __float2bfloat16(oacc[ni][2]); o1.y = __float2bfloat16(oacc[ni][3]);
        *(__nv_bfloat162*)p0 = o0;
        *(__nv_bfloat162*)p1 = o1;
    }
}

// ---------------- launcher ---------------------------------------------------
extern "C" void kernel_launch(void* const* d_in, const int* in_sizes, int n_in,
                              void* d_out, int out_size) {
    const float* x   = (const float*)d_in[0];
    const float* bt  = (const float*)d_in[1];
    const float* qw  = (const float*)d_in[2];
    const float* qb  = (const float*)d_in[3];
    const float* pw  = (const float*)d_in[4];
    const float* pb  = (const float*)d_in[5];
    const float* g1  = (const float*)d_in[6];
    const float* b1  = (const float*)d_in[7];
    const float* g2  = (const float*)d_in[8];
    const float* b2  = (const float*)d_in[9];
    const float* w1  = (const float*)d_in[10];
    const float* bb1 = (const float*)d_in[11];
    const float* w2  = (const float*)d_in[12];
    const float* bb2 = (const float*)d_in[13];
    float* out = (float*)d_out;

    // 0. convert + transpose weights to bf16 [N][K]
    convert_w_kernel<<<(192 * 576 + 255) / 256, 256>>>(WB_QKV, qw, 192, 576);
    convert_w_kernel<<<(192 * 192 + 255) / 256, 256>>>(WB_PROJ, pw, 192, 192);
    convert_w_kernel<<<(192 * 768 + 255) / 256, 256>>>(WB_W1, w1, 192, 768);
    convert_w_kernel<<<(768 * 192 + 255) / 256, 256>>>(WB_W2, w2, 768, 192);

    // 1. gather + LN1  (x -> g_xw fp32, g_a0 bf16)
    gather_ln_kernel<<<B_ * NW_ * 2, 256>>>(x, g1, b1);
    // 2. QKV GEMM: [T,192]bf16 @ [192,576] -> g_big fp32
    tgemm_bf16<OP_BIAS, 192><<<dim3(576 / 96, T_ / 128), 256>>>(AB_A0, 0, FB_BIG, WB_QKV, qb, T_, 576);
    // 3. attention (g_big fp32 -> g_a0 bf16)
    attn_mma_kernel<<<B_ * NW_ * HEADS_, 128>>>(bt);
    // 4. proj + residual: g_a0 @ pw + g_xw -> g_x1 fp32
    tgemm_bf16<OP_BIAS_RES, 192><<<dim3(192 / 96, T_ / 128), 256>>>(AB_A0, FB_XW, FB_X1, WB_PROJ, pb, T_, 192);
    // 5. LN2 (g_x1 -> g_a0 bf16)
    ln2_kernel<<<T_ / 8, 256>>>(g2, b2);
    // 6. MLP1 + GELU: g_a0 @ w1 -> g_hid bf16
    tgemm_bf16<OP_BIAS_GELU, 192><<<dim3(768 / 96, T_ / 128), 256>>>(AB_A0, 0, AB_HID, WB_W1, bb1, T_, 768);
    // 7. MLP2 + residual: g_hid @ w2 + g_x1 -> g_big[T][192] (x2)
    tgemm_bf16<OP_BIAS_RES, 768><<<dim3(192 / 96, T_ / 128), 256>>>(AB_HID, FB_X1, FB_BIG, WB_W2, bb2, T_, 192);
    // 8. scatter (g_big[T][192] -> out)
    scatter_kernel<<<B_ * NW_, 256>>>(out);
}

// round 14
// speedup vs baseline: 1.9467x; 1.0545x over previous
#include <cuda_runtime.h>
#include <cuda_bf16.h>
#include <math.h>
#include <stdint.h>

// ---------------- static config ----------------
#define B_     8
#define C_     192
#define H_     128
#define W_     128
#define WS_    8
#define SHIFT_ 4
#define HEADS_ 4
#define HD_    48
#define L_     64
#define NW_    256
#define T_     (B_*NW_*L_)         // 131072 tokens
#define HID_   768

// ---------------- scratch (static device globals, ~703 MB) -------------------
__device__ float g_xw [(size_t)T_ * C_];      // shortcut (fp32)
__device__ float g_x1 [(size_t)T_ * C_];      // residual-1 (fp32)
__device__ float g_x2 [(size_t)T_ * C_];      // x2 before scatter (fp32)
__device__ __nv_bfloat16 g_qkv[(size_t)T_ * 576];   // bf16 qkv
__device__ __nv_bfloat16 g_a0 [(size_t)T_ * C_];    // bf16 activations (LN1/attnout/LN2)
__device__ __nv_bfloat16 g_hid[(size_t)T_ * HID_];  // bf16 mlp hidden
// bf16 transposed weights [N][K]
__device__ __nv_bfloat16 g_wqkv[576 * 192];
__device__ __nv_bfloat16 g_wproj[192 * 192];
__device__ __nv_bfloat16 g_w1[768 * 192];
__device__ __nv_bfloat16 g_w2[192 * 768];

enum FBuf { FB_XW = 0, FB_X1 = 1, FB_X2 = 2 };
enum ABuf { AB_A0 = 0, AB_HID = 1, AB_QKV = 2 };
enum WBuf { WB_QKV = 0, WB_PROJ = 1, WB_W1 = 2, WB_W2 = 3 };

__device__ __forceinline__ float* fbuf_ptr(int sel) {
    switch (sel) {
        case FB_XW: return g_xw;
        case FB_X1: return g_x1;
        default:    return g_x2;
    }
}
__device__ __forceinline__ __nv_bfloat16* abuf_ptr(int sel) {
    switch (sel) {
        case AB_A0:  return g_a0;
        case AB_HID: return g_hid;
        default:     return g_qkv;
    }
}
__device__ __forceinline__ __nv_bfloat16* wbuf_ptr(int sel) {
    switch (sel) {
        case WB_QKV:  return g_wqkv;
        case WB_PROJ: return g_wproj;
        case WB_W1:   return g_w1;
        default:      return g_w2;
    }
}

__device__ __forceinline__ void mma_bf16(float c[4],
                                         const uint32_t a[4], const uint32_t b[2]) {
    asm volatile(
        "mma.sync.aligned.m16n8k16.row.col.f32.bf16.bf16.f32 "
        "{%0,%1,%2,%3}, {%4,%5,%6,%7}, {%8,%9}, {%0,%1,%2,%3};"
        : "+f"(c[0]), "+f"(c[1]), "+f"(c[2]), "+f"(c[3])
        : "r"(a[0]), "r"(a[1]), "r"(a[2]), "r"(a[3]), "r"(b[0]), "r"(b[1]));
}

__device__ __forceinline__ void cp_async16(void* smem, const void* gmem) {
    uint32_t s = (uint32_t)__cvta_generic_to_shared(smem);
    asm volatile("cp.async.ca.shared.global [%0], [%1], 16;" :: "r"(s), "l"(gmem));
}

__device__ __forceinline__ uint32_t pack_bf16x2(float lo, float hi) {
    __nv_bfloat162 h = __floats2bfloat162_rn(lo, hi);
    return *(uint32_t*)&h;
}

// ---------------- weight convert + transpose: fp32[K][N] -> bf16[N][K] ------
__global__ __launch_bounds__(256) void convert_w_kernel(int selW, const float* __restrict__ src,
                                                        int K, int N) {
    __nv_bfloat16* dst = wbuf_ptr(selW);
    int i = blockIdx.x * 256 + threadIdx.x;
    if (i < K * N) {
        int n = i / K, k = i - n * K;
        dst[i] = __float2bfloat16(src[(long)k * N + n]);
    }
}

// ---------------- fused gather + LN1: x -> g_xw (fp32) + g_a0 (bf16) --------
#define S2_STR 196
__global__ __launch_bounds__(256) void gather_ln_kernel(const float* __restrict__ x,
                                                        const float* __restrict__ gam,
                                                        const float* __restrict__ bet) {
    __shared__ float s2[32 * S2_STR];
    __shared__ float sg[192], sb[192];
    __shared__ float smu[32], srs[32];
    int blk = blockIdx.x;
    int half = blk & 1;
    int bn = blk >> 1;
    int b = bn / NW_;
    int n = bn % NW_;
    int wh = n >> 4, ww = n & 15;
    long tokbase = (long)bn * 64 + half * 32;
    int tid = threadIdx.x;

    for (int t = tid; t < 192; t += 256) { sg[t] = gam[t]; sb[t] = bet[t]; }

    #pragma unroll
    for (int ci = 0; ci < 4; ci++) {
        #pragma unroll
        for (int t = 0; t < 6; t++) {
            int idx = tid + t * 256;
            int c = idx >> 5, l = idx & 31;
            int hr = (wh * 8 + half * 4 + (l >> 3) + SHIFT_) & 127;
            int wc = (ww * 8 + (l & 7) + SHIFT_) & 127;
            s2[l * S2_STR + ci * 48 + c] = x[(((b * C_ + ci * 48 + c) * H_ + hr) << 7) + wc];
        }
    }
    __syncthreads();

    int l = tid >> 3, part = tid & 7;
    float sum = 0.f;
    #pragma unroll
    for (int u = 0; u < 24; u++) sum += s2[l * S2_STR + part + 8 * u];
    sum += __shfl_xor_sync(0xffffffffu, sum, 1);
    sum += __shfl_xor_sync(0xffffffffu, sum, 2);
    sum += __shfl_xor_sync(0xffffffffu, sum, 4);
    float mu = sum * (1.0f / 192.0f);
    float sq = 0.f;
    #pragma unroll
    for (int u = 0; u < 24; u++) {
        float d = s2[l * S2_STR + part + 8 * u] - mu;
        sq += d * d;
    }
    sq += __shfl_xor_sync(0xffffffffu, sq, 1);
    sq += __shfl_xor_sync(0xffffffffu, sq, 2);
    sq += __shfl_xor_sync(0xffffffffu, sq, 4);
    float rstd = rsqrtf(sq * (1.0f / 192.0f) + 1e-5f);
    if (part == 0) { smu[l] = mu; srs[l] = rstd; }
    __syncthreads();

    for (int idx = tid; idx < 32 * 192; idx += 256) {
        int l2 = idx / 192, c = idx - l2 * 192;
        float v = s2[l2 * S2_STR + c];
        long off = (tokbase + l2) * C_ + c;
        g_xw[off] = v;
        g_a0[off] = __float2bfloat16((v - smu[l2]) * srs[l2] * sg[c] + sb[c]);
    }
}

// ---------------- LN2: g_x1 (fp32) -> g_a0 (bf16) ---------------------------
__global__ __launch_bounds__(256) void ln2_kernel(const float* __restrict__ gam,
                                                  const float* __restrict__ bet) {
    int warp = threadIdx.x >> 5;
    int lane = threadIdx.x & 31;
    long tok = (long)blockIdx.x * 8 + warp;
    const float* row = g_x1 + tok * C_;
    float v[6];
    float sum = 0.f;
    #pragma unroll
    for (int u = 0; u < 6; u++) { v[u] = row[lane + 32 * u]; sum += v[u]; }
    #pragma unroll
    for (int o = 16; o; o >>= 1) sum += __shfl_xor_sync(0xffffffffu, sum, o);
    float mu = sum * (1.0f / 192.0f);
    float sq = 0.f;
    #pragma unroll
    for (int u = 0; u < 6; u++) { float d = v[u] - mu; sq += d * d; }
    #pragma unroll
    for (int o = 16; o; o >>= 1) sq += __shfl_xor_sync(0xffffffffu, sq, o);
    float rstd = rsqrtf(sq * (1.0f / 192.0f) + 1e-5f);
    __nv_bfloat16* orow = g_a0 + tok * C_;
    #pragma unroll
    for (int u = 0; u < 6; u++) {
        int c = lane + 32 * u;
        orow[c] = __float2bfloat16((v[u] - mu) * rstd * gam[c] + bet[c]);
    }
}

// ---------------- scatter: g_x2 -> out (reverse window + roll) --------------
__global__ __launch_bounds__(256) void scatter_kernel(float* __restrict__ out) {
    __shared__ float s[48 * 65];
    int blk = blockIdx.x;
    int b = blk / NW_;
    int n = blk % NW_;
    int wh = n >> 4, ww = n & 15;
    long tokbase = (long)blk * L_;
    int tid = threadIdx.x;
    for (int ci = 0; ci < 4; ci++) {
        #pragma unroll
        for (int t = 0; t < 12; t++) {
            int idx = tid + t * 256;
            int l = idx / 48, c = idx % 48;
            s[c * 65 + l] = g_x2[(tokbase + l) * C_ + ci * 48 + c];
        }
        __syncthreads();
        #pragma unroll
        for (int t = 0; t < 12; t++) {
            int idx = tid + t * 256;
            int c = idx >> 6, l = idx & 63;
            int hr = (wh * 8 + (l >> 3) + SHIFT_) & 127;
            int wc = (ww * 8 + (l & 7) + SHIFT_) & 127;
            out[(((b * C_ + ci * 48 + c) * H_ + hr) << 7) + wc] = s[c * 65 + l];
        }
        __syncthreads();
    }
}

// ---------------- bf16 tensor-core GEMM -------------------------------------
// 128x96 tile, 8 warps, warp 32x48, k-chunk 16, cp.async double-buffer.
// OP_BIAS / OP_BIAS_GELU write bf16 (abuf); OP_BIAS_RES writes fp32 + residual.
enum { OP_BIAS = 0, OP_BIAS_RES = 1, OP_BIAS_GELU = 2 };

template<int OP, int K>
__global__ __launch_bounds__(256) void tgemm_bf16(int selA, int selR, int selO,
                                                  int selW,
                                                  const float* __restrict__ bias,
                                                  int M, int N) {
    const __nv_bfloat16* A = abuf_ptr(selA);
    const __nv_bfloat16* Wt = wbuf_ptr(selW);
    const float* R = fbuf_ptr(selR);

    __shared__ uint32_t As[2][128][12];
    __shared__ uint32_t Bs[2][96][12];

    int tid = threadIdx.x;
    int warp = tid >> 5;
    int lane = tid & 31;
    int gid = lane >> 2;
    int tig = lane & 3;
    int wm = (warp >> 1) * 32;
    int wn = (warp & 1) * 48;
    int m0 = blockIdx.y * 128;
    int n0 = blockIdx.x * 96;

    int a_row = tid >> 1, a_h = tid & 1;
    int b_row = tid >> 1, b_h = tid & 1;

    float acc[2][6][4];
    #pragma unroll
    for (int i = 0; i < 2; i++)
        #pragma unroll
        for (int j = 0; j < 6; j++)
            #pragma unroll
            for (int c = 0; c < 4; c++) acc[i][j][c] = 0.f;

    const int NKC = K >> 4;

    cp_async16((char*)&As[0][a_row][0] + a_h * 16, A + (long)(m0 + a_row) * K + a_h * 8);
    if (tid < 192)
        cp_async16((char*)&Bs[0][b_row][0] + b_h * 16, Wt + (long)(n0 + b_row) * K + b_h * 8);
    asm volatile("cp.async.commit_group;");

    int bf = 0;
    for (int it = 0; it < NKC; it++) {
        asm volatile("cp.async.wait_group 0;");
        __syncthreads();
        if (it + 1 < NKC) {
            int kk = (it + 1) << 4;
            int nb = bf ^ 1;
            cp_async16((char*)&As[nb][a_row][0] + a_h * 16,
                       A + (long)(m0 + a_row) * K + kk + a_h * 8);
            if (tid < 192)
                cp_async16((char*)&Bs[nb][b_row][0] + b_h * 16,
                           Wt + (long)(n0 + b_row) * K + kk + b_h * 8);
            asm volatile("cp.async.commit_group;");
        }

        uint32_t a[2][4], b[6][2];
        #pragma unroll
        for (int mi = 0; mi < 2; mi++) {
            int mrow = wm + mi * 16 + gid;
            a[mi][0] = As[bf][mrow][tig];
            a[mi][1] = As[bf][mrow + 8][tig];
            a[mi][2] = As[bf][mrow][tig + 4];
            a[mi][3] = As[bf][mrow + 8][tig + 4];
        }
        #pragma unroll
        for (int ni = 0; ni < 6; ni++) {
            int ncol = wn + ni * 8 + gid;
            b[ni][0] = Bs[bf][ncol][tig];
            b[ni][1] = Bs[bf][ncol][tig + 4];
        }
        #pragma unroll
        for (int mi = 0; mi < 2; mi++)
            #pragma unroll
            for (int ni = 0; ni < 6; ni++)
                mma_bf16(acc[mi][ni], a[mi], b[ni]);

        bf ^= 1;
    }

    #pragma unroll
    for (int mi = 0; mi < 2; mi++) {
        #pragma unroll
        for (int ni = 0; ni < 6; ni++) {
            int col = n0 + wn + ni * 8 + tig * 2;
            float bv0 = bias[col], bv1 = bias[col + 1];
            #pragma unroll
            for (int h = 0; h < 2; h++) {
                long row = m0 + wm + mi * 16 + gid + h * 8;
                float v0 = acc[mi][ni][h * 2 + 0] + bv0;
                float v1 = acc[mi][ni][h * 2 + 1] + bv1;
                if (OP == OP_BIAS_GELU) {
                    v0 = 0.5f * v0 * (1.0f + erff(v0 * 0.70710678118654752f));
                    v1 = 0.5f * v1 * (1.0f + erff(v1 * 0.70710678118654752f));
                }
                if (OP == OP_BIAS || OP == OP_BIAS_GELU) {
                    __nv_bfloat16* Oh = abuf_ptr(selO);
                    __nv_bfloat162 p;
                    p.x = __float2bfloat16(v0);
                    p.y = __float2bfloat16(v1);
                    *(__nv_bfloat162*)(Oh + row * N + col) = p;
                } else {
                    v0 += R[row * N + col];
                    v1 += R[row * N + col + 1];
                    float* Of = fbuf_ptr(selO);
                    *(float2*)(Of + row * N + col) = make_float2(v0, v1);
                }
            }
        }
    }
}

// ---------------- bf16 tensor-core windowed attention -----------------------
// one 128-thread block per (b, window, head); 4 warps, 16 rows each.
// Q/K rows [l][d] bf16, u32 stride 28 (28*gid+tig permutes mod 32).
// V d-major [d][l] stride 36; P [r][j] stride 36 (4*gid+tig permutes).
#define QS 28
#define VS 36
#define PS 36

__global__ __launch_bounds__(128) void attn_bf16_kernel(const float* __restrict__ bias_table) {
    __shared__ uint32_t sQK[2 * 64 * QS];   // Q at 0, K at 1792; P aliases Q (needs 64*36=2304 <= 3584)
    __shared__ uint32_t sV[48 * VS];
    __shared__ float bb[225];

    uint32_t* sQ = sQK;
    uint32_t* sK = sQK + 64 * QS;
    uint32_t* sP = sQK;

    int blk = blockIdx.x;
    int head = blk & 3;
    int bn = blk >> 2;
    int n = bn % NW_;
    int wh = n >> 4, ww = n & 15;
    long tokbase = (long)bn * 64;
    int tid = threadIdx.x;
    int warp = tid >> 5;
    int lane = tid & 31;
    int gid = lane >> 2;
    int tig = lane & 3;

    for (int t = tid; t < 225; t += 128) bb[t] = bias_table[head * 225 + t];

    // load Q,K rows (raw u32 copies); V transposed to d-major
    uint16_t* sv16 = (uint16_t*)sV;
    for (int t = tid; t < 384; t += 128) {     // 64 rows x 6 uint4
        int l = t / 6, q4 = t % 6;
        const __nv_bfloat16* base = g_qkv + (tokbase + l) * 576 + head * 48 + q4 * 8;
        uint4 q = *(const uint4*)(base);
        uint4 k = *(const uint4*)(base + 192);
        uint4 v = *(const uint4*)(base + 384);
        *(uint4*)&sQ[l * QS + q4 * 4] = q;
        *(uint4*)&sK[l * QS + q4 * 4] = k;
        uint16_t* v16 = (uint16_t*)&v;
        #pragma unroll
        for (int j = 0; j < 8; j++)
            sv16[(q4 * 8 + j) * (VS * 2) + l] = v16[j];
    }
    __syncthreads();

    // scores: S = Q K^T (raw), 3 bf16 k-chunks over d=48
    int r0 = warp * 16 + gid, r1 = r0 + 8;
    float acc[8][4];
    #pragma unroll
    for (int ni = 0; ni < 8; ni++)
        #pragma unroll
        for (int c = 0; c < 4; c++) acc[ni][c] = 0.f;

    #pragma unroll
    for (int kc = 0; kc < 3; kc++) {
        uint32_t a[4];
        a[0] = sQ[r0 * QS + kc * 8 + tig];
        a[1] = sQ[r1 * QS + kc * 8 + tig];
        a[2] = sQ[r0 * QS + kc * 8 + tig + 4];
        a[3] = sQ[r1 * QS + kc * 8 + tig + 4];
        #pragma unroll
        for (int ni = 0; ni < 8; ni++) {
            uint32_t b[2];
            b[0] = sK[(ni * 8 + gid) * QS + kc * 8 + tig];
            b[1] = sK[(ni * 8 + gid) * QS + kc * 8 + tig + 4];
            mma_bf16(acc[ni], a, b);
        }
    }

    // scale + bias + shift mask + softmax
    const float scale = 0.14433756729740643f;   // 1/sqrt(48)
    int ih0 = r0 >> 3, iw0 = r0 & 7;
    int ih1 = r1 >> 3, iw1 = r1 & 7;
    int reg_i0 = ((wh == 15) ? (ih0 < 4 ? 3 : 6) : 0) + ((ww == 15) ? (iw0 < 4 ? 1 : 2) : 0);
    int reg_i1 = ((wh == 15) ? (ih1 < 4 ? 3 : 6) : 0) + ((ww == 15) ? (iw1 < 4 ? 1 : 2) : 0);

    float mx0 = -1e30f, mx1 = -1e30f;
    #pragma unroll
    for (int ni = 0; ni < 8; ni++) {
        #pragma unroll
        for (int hh = 0; hh < 2; hh++) {
            int j = ni * 8 + tig * 2 + hh;
            int jh = j >> 3, jw = j & 7;
            int reg_j = ((wh == 15) ? (jh < 4 ? 3 : 6) : 0) + ((ww == 15) ? (jw < 4 ? 1 : 2) : 0);
            float bt0 = (reg_i0 != reg_j) ? -100.0f : bb[(ih0 - jh + 7) * 15 + (iw0 - jw + 7)];
            float bt1 = (reg_i1 != reg_j) ? -100.0f : bb[(ih1 - jh + 7) * 15 + (iw1 - jw + 7)];
            acc[ni][hh]     = acc[ni][hh] * scale + bt0;
            acc[ni][2 + hh] = acc[ni][2 + hh] * scale + bt1;
            mx0 = fmaxf(mx0, acc[ni][hh]);
            mx1 = fmaxf(mx1, acc[ni][2 + hh]);
        }
    }
    mx0 = fmaxf(mx0, __shfl_xor_sync(0xffffffffu, mx0, 1));
    mx0 = fmaxf(mx0, __shfl_xor_sync(0xffffffffu, mx0, 2));
    mx1 = fmaxf(mx1, __shfl_xor_sync(0xffffffffu, mx1, 1));
    mx1 = fmaxf(mx1, __shfl_xor_sync(0xffffffffu, mx1, 2));
    float s0 = 0.f, s1 = 0.f;
    #pragma unroll
    for (int ni = 0; ni < 8; ni++) {
        #pragma unroll
        for (int hh = 0; hh < 2; hh++) {
            acc[ni][hh]     = __expf(acc[ni][hh] - mx0);     s0 += acc[ni][hh];
            acc[ni][2 + hh] = __expf(acc[ni][2 + hh] - mx1); s1 += acc[ni][2 + hh];
        }
    }
    s0 += __shfl_xor_sync(0xffffffffu, s0, 1);
    s0 += __shfl_xor_sync(0xffffffffu, s0, 2);
    s1 += __shfl_xor_sync(0xffffffffu, s1, 1);
    s1 += __shfl_xor_sync(0xffffffffu, s1, 2);
    float inv0 = 1.0f / s0, inv1 = 1.0f / s1;

    __syncthreads();   // all warps done with sQ/sK before P overwrites

    #pragma unroll
    for (int ni = 0; ni < 8; ni++) {
        sP[r0 * PS + ni * 4 + tig] = pack_bf16x2(acc[ni][0] * inv0, acc[ni][1] * inv0);
        sP[r1 * PS + ni * 4 + tig] = pack_bf16x2(acc[ni][2] * inv1, acc[ni][3] * inv1);
    }
    __syncthreads();

    // O = P V : 4 bf16 k-chunks over l=64
    float oacc[6][4];
    #pragma unroll
    for (int ni = 0; ni < 6; ni++)
        #pragma unroll
        for (int c = 0; c < 4; c++) oacc[ni][c] = 0.f;

    #pragma unroll
    for (int kt = 0; kt < 4; kt++) {
        uint32_t a[4];
        a[0] = sP[r0 * PS + kt * 8 + tig];
        a[1] = sP[r1 * PS + kt * 8 + tig];
        a[2] = sP[r0 * PS + kt * 8 + tig + 4];
        a[3] = sP[r1 * PS + kt * 8 + tig + 4];
        #pragma unroll
        for (int ni = 0; ni < 6; ni++) {
            uint32_t b[2];
            b[0] = sV[(ni * 8 + gid) * VS + kt * 8 + tig];
            b[1] = sV[(ni * 8 + gid) * VS + kt * 8 + tig + 4];
            mma_bf16(oacc[ni], a, b);
        }
    }

    #pragma unroll
    for (int ni = 0; ni < 6; ni++) {
        int col = ni * 8 + tig * 2;
        __nv_bfloat16* p0 = g_a0 + (tokbase + r0) * C_ + head * 48 + col;
        __nv_bfloat16* p1 = g_a0 + (tokbase + r1) * C_ + head * 48 + col;
        __nv_bfloat162 o0, o1;
        o0.x = __float2bfloat16(oacc[ni][0]); o0.y = __float2bfloat16(oacc[ni][1]);
        o1.x = __float2bfloat16(oacc[ni][2]); o1.y = __float2bfloat16(oacc[ni][3]);
        *(__nv_bfloat162*)p0 = o0;
        *(__nv_bfloat162*)p1 = o1;
    }
}

// ---------------- launcher ---------------------------------------------------
extern "C" void kernel_launch(void* const* d_in, const int* in_sizes, int n_in,
                              void* d_out, int out_size) {
    const float* x   = (const float*)d_in[0];
    const float* bt  = (const float*)d_in[1];
    const float* qw  = (const float*)d_in[2];
    const float* qb  = (const float*)d_in[3];
    const float* pw  = (const float*)d_in[4];
    const float* pb  = (const float*)d_in[5];
    const float* g1  = (const float*)d_in[6];
    const float* b1  = (const float*)d_in[7];
    const float* g2  = (const float*)d_in[8];
    const float* b2  = (const float*)d_in[9];
    const float* w1  = (const float*)d_in[10];
    const float* bb1 = (const float*)d_in[11];
    const float* w2  = (const float*)d_in[12];
    const float* bb2 = (const float*)d_in[13];
    float* out = (float*)d_out;

    // 0. convert + transpose weights to bf16 [N][K]
    convert_w_kernel<<<(192 * 576 + 255) / 256, 256>>>(WB_QKV, qw, 192, 576);
    convert_w_kernel<<<(192 * 192 + 255) / 256, 256>>>(WB_PROJ, pw, 192, 192);
    convert_w_kernel<<<(192 * 768 + 255) / 256, 256>>>(WB_W1, w1, 192, 768);
    convert_w_kernel<<<(768 * 192 + 255) / 256, 256>>>(WB_W2, w2, 768, 192);

    // 1. gather + LN1  (x -> g_xw fp32, g_a0 bf16)
    gather_ln_kernel<<<B_ * NW_ * 2, 256>>>(x, g1, b1);
    // 2. QKV GEMM: bf16 out -> g_qkv
    tgemm_bf16<OP_BIAS, 192><<<dim3(576 / 96, T_ / 128), 256>>>(AB_A0, 0, AB_QKV, WB_QKV, qb, T_, 576);
    // 3. bf16 attention (g_qkv -> g_a0)
    attn_bf16_kernel<<<B_ * NW_ * HEADS_, 128>>>(bt);
    // 4. proj + residual: g_a0 @ pw + g_xw -> g_x1 fp32
    tgemm_bf16<OP_BIAS_RES, 192><<<dim3(192 / 96, T_ / 128), 256>>>(AB_A0, FB_XW, FB_X1, WB_PROJ, pb, T_, 192);
    // 5. LN2 (g_x1 -> g_a0 bf16)
    ln2_kernel<<<T_ / 8, 256>>>(g2, b2);
    // 6. MLP1 + GELU: g_a0 @ w1 -> g_hid bf16
    tgemm_bf16<OP_BIAS_GELU, 192><<<dim3(768 / 96, T_ / 128), 256>>>(AB_A0, 0, AB_HID, WB_W1, bb1, T_, 768);
    // 7. MLP2 + residual: g_hid @ w2 + g_x1 -> g_x2 fp32
    tgemm_bf16<OP_BIAS_RES, 768><<<dim3(192 / 96, T_ / 128), 256>>>(AB_HID, FB_X1, FB_X2, WB_W2, bb2, T_, 192);
    // 8. scatter (g_x2 -> out)
    scatter_kernel<<<B_ * NW_, 256>>>(out);
}